// round 1
// baseline (speedup 1.0000x reference)
#include <cuda_runtime.h>
#include <math.h>
#include <stdint.h>

#define LLAYERS 6
#define DMODEL  512
#define NH      8
#define HD      64
#define NVOCAB  10000
#define NB      32
#define NS      64
#define NNR     196
#define NTOK    (NB*NS)     // 2048
#define NCTOK   (NB*NNR)    // 6272

// ---------------- scratch (no cudaMalloc allowed) ----------------
__device__ float g_act[NTOK*DMODEL];
__device__ float g_q  [NTOK*DMODEL];
__device__ float g_k  [NTOK*DMODEL];
__device__ float g_v  [NTOK*DMODEL];
__device__ float g_ao [NTOK*DMODEL];
__device__ float g_kc [NCTOK*DMODEL];
__device__ float g_vc [NCTOK*DMODEL];
__device__ float g_gq [NB*DMODEL];

// ---------------- embedding + positional encoding ----------------
__global__ void embed_kernel(const int* __restrict__ x, const float* __restrict__ emb,
                             float* __restrict__ out) {
    int t = blockIdx.x;          // token index 0..2047
    int s = t % NS;              // sequence position
    int tok = x[t];
    for (int d = threadIdx.x; d < DMODEL; d += blockDim.x) {
        int j = d >> 1;
        float ang = (float)s * powf(10000.0f, -(2.0f*(float)j)/(float)DMODEL);
        float pe = (d & 1) ? cosf(ang) : sinf(ang);
        out[t*DMODEL + d] = emb[tok*DMODEL + d] + pe;
    }
}

// ---------------- tiled SGEMM: C[M,N] = A[M,K] @ W[K,N] (+rowBias)(+colBias) ----
// rowBias: if non-null, adds rowBias[(m>>6)*N + n]  (per-batch broadcast, rows are b*64+s)
// colBias: if non-null, adds colBias[n]
__global__ void gemm_kernel(const float* __restrict__ A, const float* __restrict__ W,
                            float* __restrict__ C, int M, int N, int K,
                            const float* __restrict__ rowBias,
                            const float* __restrict__ colBias) {
    __shared__ float As[16][68];   // As[kk][m_local]  (transposed for vector LDS)
    __shared__ float Bs[16][68];   // Bs[kk][n_local]
    const int tx = threadIdx.x, ty = threadIdx.y;
    const int tid = ty*16 + tx;
    const int m0 = blockIdx.y * 64;
    const int n0 = blockIdx.x * 64;

    float acc[4][4] = {};

    const int arow = tid >> 2;          // 0..63
    const int ac4  = (tid & 3) * 4;     // 0,4,8,12
    const int brow = tid >> 4;          // 0..15
    const int bc4  = (tid & 15) * 4;    // 0..60
    const bool aok = (m0 + arow) < M;
    const float* Aptr = A + (size_t)(m0 + arow) * K;

    for (int k0 = 0; k0 < K; k0 += 16) {
        // A tile (64x16) -> transposed smem
        float4 av = make_float4(0.f,0.f,0.f,0.f);
        if (aok) av = *(const float4*)(Aptr + k0 + ac4);
        As[ac4+0][arow] = av.x; As[ac4+1][arow] = av.y;
        As[ac4+2][arow] = av.z; As[ac4+3][arow] = av.w;
        // B tile (16x64)
        {
            int n = n0 + bc4;
            const float* Wp = W + (size_t)(k0 + brow) * N + n;
            float4 bv;
            if (n + 3 < N) {
                bv = *(const float4*)Wp;
            } else {
                bv.x = (n+0 < N) ? Wp[0] : 0.f;
                bv.y = (n+1 < N) ? Wp[1] : 0.f;
                bv.z = (n+2 < N) ? Wp[2] : 0.f;
                bv.w = (n+3 < N) ? Wp[3] : 0.f;
            }
            *(float4*)&Bs[brow][bc4] = bv;
        }
        __syncthreads();
        #pragma unroll
        for (int kk = 0; kk < 16; kk++) {
            float4 a = *(const float4*)&As[kk][ty*4];
            float4 b = *(const float4*)&Bs[kk][tx*4];
            acc[0][0] += a.x*b.x; acc[0][1] += a.x*b.y; acc[0][2] += a.x*b.z; acc[0][3] += a.x*b.w;
            acc[1][0] += a.y*b.x; acc[1][1] += a.y*b.y; acc[1][2] += a.y*b.z; acc[1][3] += a.y*b.w;
            acc[2][0] += a.z*b.x; acc[2][1] += a.z*b.y; acc[2][2] += a.z*b.z; acc[2][3] += a.z*b.w;
            acc[3][0] += a.w*b.x; acc[3][1] += a.w*b.y; acc[3][2] += a.w*b.z; acc[3][3] += a.w*b.w;
        }
        __syncthreads();
    }
    #pragma unroll
    for (int i = 0; i < 4; i++) {
        int m = m0 + ty*4 + i;
        if (m >= M) continue;
        #pragma unroll
        for (int j = 0; j < 4; j++) {
            int n = n0 + tx*4 + j;
            if (n >= N) continue;
            float v = acc[i][j];
            if (rowBias) v += rowBias[(size_t)(m >> 6) * N + n];
            if (colBias) v += colBias[n];
            C[(size_t)m*N + n] = v;
        }
    }
}

// ---------------- fused attention (one CTA per (b,h)), online softmax ----------
// Q rows: [b*NS+s][h*HD + d] in a [NTOK, DMODEL] buffer.
// K/V rows: [b*kvTokens + key][h*HD + d].
#define ATTN_SMEM_FLOATS (3*64*65 + 8*64)
template<bool CAUSAL>
__global__ void attn_kernel(const float* __restrict__ Q, const float* __restrict__ Kb,
                            const float* __restrict__ Vb, float* __restrict__ O,
                            int skeys, int kvTokens) {
    extern __shared__ float sm[];
    float* Qs = sm;                 // [64][65]
    float* Ks = sm + 64*65;         // [64][65]
    float* Vs = sm + 2*64*65;       // [64][65]
    float* Ps = sm + 3*64*65;       // [8][64] per-warp probabilities

    const int b = blockIdx.x / NH, h = blockIdx.x % NH;
    const int tid = threadIdx.x, w = tid >> 5, lane = tid & 31;

    for (int i = tid; i < 64*64; i += 256) {
        int r = i >> 6, c = i & 63;
        Qs[r*65 + c] = Q[(size_t)(b*NS + r)*DMODEL + h*HD + c];
    }
    float mrow[8], lrow[8], a0[8], a1[8];
    #pragma unroll
    for (int i = 0; i < 8; i++) { mrow[i] = -1e30f; lrow[i] = 0.f; a0[i] = 0.f; a1[i] = 0.f; }
    __syncthreads();

    const int nch = (skeys + 63) >> 6;
    for (int ch = 0; ch < nch; ch++) {
        const int kb = ch * 64;
        const int cnt = min(64, skeys - kb);
        for (int i = tid; i < 64*64; i += 256) {
            int r = i >> 6, c = i & 63;
            float kv = 0.f, vv = 0.f;
            if (r < cnt) {
                size_t off = (size_t)(b*kvTokens + kb + r)*DMODEL + h*HD + c;
                kv = Kb[off]; vv = Vb[off];
            }
            Ks[r*65 + c] = kv; Vs[r*65 + c] = vv;
        }
        __syncthreads();

        #pragma unroll
        for (int rr = 0; rr < 8; rr++) {
            const int r = w*8 + rr;
            const float* qr = &Qs[r*65];
            float d0 = 0.f, d1 = 0.f;
            #pragma unroll 8
            for (int d = 0; d < 64; d++) {
                float qd = qr[d];
                d0 += qd * Ks[lane*65 + d];
                d1 += qd * Ks[(lane+32)*65 + d];
            }
            float s0 = d0 * 0.125f, s1 = d1 * 0.125f;   // / sqrt(64)
            bool v0 = (lane      < cnt) && (!CAUSAL || (kb + lane)      <= r);
            bool v1 = (lane + 32 < cnt) && (!CAUSAL || (kb + lane + 32) <= r);
            if (!v0) s0 = -1e30f;
            if (!v1) s1 = -1e30f;
            float cm = fmaxf(s0, s1);
            #pragma unroll
            for (int o = 16; o > 0; o >>= 1) cm = fmaxf(cm, __shfl_xor_sync(0xffffffffu, cm, o));
            float nm = fmaxf(mrow[rr], cm);
            float corr = __expf(mrow[rr] - nm);
            float p0 = v0 ? __expf(s0 - nm) : 0.f;
            float p1 = v1 ? __expf(s1 - nm) : 0.f;
            float ps = p0 + p1;
            #pragma unroll
            for (int o = 16; o > 0; o >>= 1) ps += __shfl_xor_sync(0xffffffffu, ps, o);
            lrow[rr] = lrow[rr]*corr + ps;
            mrow[rr] = nm;
            a0[rr] *= corr; a1[rr] *= corr;
            Ps[w*64 + lane]      = p0;
            Ps[w*64 + lane + 32] = p1;
            __syncwarp();
            float acc0 = 0.f, acc1 = 0.f;
            #pragma unroll 8
            for (int k = 0; k < 64; k++) {
                float p = Ps[w*64 + k];
                acc0 += p * Vs[k*65 + lane];
                acc1 += p * Vs[k*65 + lane + 32];
            }
            a0[rr] += acc0; a1[rr] += acc1;
            __syncwarp();
        }
        __syncthreads();
    }
    #pragma unroll
    for (int rr = 0; rr < 8; rr++) {
        int r = w*8 + rr;
        float inv = 1.0f / lrow[rr];
        size_t o = (size_t)(b*NS + r)*DMODEL + h*HD;
        O[o + lane]      = a0[rr] * inv;
        O[o + lane + 32] = a1[rr] * inv;
    }
}

// ---------------- final row softmax over VOCAB (in-place on d_out) ------------
__global__ void softmax_kernel(float* __restrict__ out) {
    __shared__ float buf[NVOCAB];
    __shared__ float red[8];
    const int tid = threadIdx.x, w = tid >> 5, lane = tid & 31;
    float* p = out + (size_t)blockIdx.x * NVOCAB;

    float mx = -1e30f;
    for (int i = tid; i < NVOCAB; i += 256) { float v = p[i]; buf[i] = v; mx = fmaxf(mx, v); }
    #pragma unroll
    for (int o = 16; o > 0; o >>= 1) mx = fmaxf(mx, __shfl_xor_sync(0xffffffffu, mx, o));
    if (lane == 0) red[w] = mx;
    __syncthreads();
    mx = red[0];
    #pragma unroll
    for (int i = 1; i < 8; i++) mx = fmaxf(mx, red[i]);
    __syncthreads();

    float sum = 0.f;
    for (int i = tid; i < NVOCAB; i += 256) { float e = __expf(buf[i] - mx); buf[i] = e; sum += e; }
    #pragma unroll
    for (int o = 16; o > 0; o >>= 1) sum += __shfl_xor_sync(0xffffffffu, sum, o);
    if (lane == 0) red[w] = sum;
    __syncthreads();
    sum = 0.f;
    #pragma unroll
    for (int i = 0; i < 8; i++) sum += red[i];
    float inv = 1.0f / sum;
    for (int i = tid; i < NVOCAB; i += 256) p[i] = buf[i] * inv;
}

// ---------------- host launcher ----------------
static inline void launch_gemm(const float* A, const float* W, float* C,
                               int M, int N, int K,
                               const float* rb, const float* cb) {
    dim3 grid((N + 63) / 64, (M + 63) / 64), block(16, 16);
    gemm_kernel<<<grid, block>>>(A, W, C, M, N, K, rb, cb);
}

extern "C" void kernel_launch(void* const* d_in, const int* in_sizes, int n_in,
                              void* d_out, int out_size) {
    const int*   x   = (const int*)  d_in[0];
    const float* Kin = (const float*)d_in[1];
    const float* Vin = (const float*)d_in[2];
    const float* g   = (const float*)d_in[3];
    int i = 4;
    if (i < n_in && in_sizes[i] == 1) i++;     // skip batch_size scalar if serialized
    const float* emb  = (const float*)d_in[i++];
    const float* Wq_s = (const float*)d_in[i++];
    const float* Wk_s = (const float*)d_in[i++];
    const float* Wv_s = (const float*)d_in[i++];
    const float* Wo_s = (const float*)d_in[i++];
    const float* Wq_c = (const float*)d_in[i++];
    const float* Wg_c = (const float*)d_in[i++];
    const float* Wk_c = (const float*)d_in[i++];
    const float* Wv_c = (const float*)d_in[i++];
    const float* Wo_c = (const float*)d_in[i++];
    const float* Wf   = (const float*)d_in[i++];
    const float* bf   = (const float*)d_in[i++];

    float *act, *q, *k, *v, *ao, *kc, *vc, *gq;
    cudaGetSymbolAddress((void**)&act, g_act);
    cudaGetSymbolAddress((void**)&q,   g_q);
    cudaGetSymbolAddress((void**)&k,   g_k);
    cudaGetSymbolAddress((void**)&v,   g_v);
    cudaGetSymbolAddress((void**)&ao,  g_ao);
    cudaGetSymbolAddress((void**)&kc,  g_kc);
    cudaGetSymbolAddress((void**)&vc,  g_vc);
    cudaGetSymbolAddress((void**)&gq,  g_gq);

    const int ATTN_SMEM = ATTN_SMEM_FLOATS * (int)sizeof(float);
    cudaFuncSetAttribute(attn_kernel<true>,  cudaFuncAttributeMaxDynamicSharedMemorySize, ATTN_SMEM);
    cudaFuncSetAttribute(attn_kernel<false>, cudaFuncAttributeMaxDynamicSharedMemorySize, ATTN_SMEM);

    // embedding + positional encoding
    embed_kernel<<<NTOK, 128>>>(x, emb, act);

    const size_t WSZ = (size_t)DMODEL * DMODEL;
    for (int l = 0; l < LLAYERS; l++) {
        // ---- masked self-attention ----
        launch_gemm(act, Wq_s + l*WSZ, q, NTOK, DMODEL, DMODEL, nullptr, nullptr);
        launch_gemm(act, Wk_s + l*WSZ, k, NTOK, DMODEL, DMODEL, nullptr, nullptr);
        launch_gemm(act, Wv_s + l*WSZ, v, NTOK, DMODEL, DMODEL, nullptr, nullptr);
        attn_kernel<true><<<NB*NH, 256, ATTN_SMEM>>>(q, k, v, ao, NS, NS);
        launch_gemm(ao, Wo_s + l*WSZ, act, NTOK, DMODEL, DMODEL, nullptr, nullptr);

        // ---- global-adaptive cross-attention ----
        launch_gemm(g,   Wg_c + l*WSZ, gq, NB,   DMODEL, DMODEL, nullptr, nullptr);
        launch_gemm(act, Wq_c + l*WSZ, q,  NTOK, DMODEL, DMODEL, gq,      nullptr);
        launch_gemm(Kin, Wk_c + l*WSZ, kc, NCTOK, DMODEL, DMODEL, nullptr, nullptr);
        launch_gemm(Vin, Wv_c + l*WSZ, vc, NCTOK, DMODEL, DMODEL, nullptr, nullptr);
        attn_kernel<false><<<NB*NH, 256, ATTN_SMEM>>>(q, kc, vc, ao, NNR, NNR);
        launch_gemm(ao, Wo_c + l*WSZ, act, NTOK, DMODEL, DMODEL, nullptr, nullptr);
    }

    // ---- final projection + softmax ----
    launch_gemm(act, Wf, (float*)d_out, NTOK, NVOCAB, DMODEL, nullptr, bf);
    softmax_kernel<<<NTOK, 256>>>((float*)d_out);
}

// round 2
// speedup vs baseline: 1.1898x; 1.1898x over previous
#include <cuda_runtime.h>
#include <math.h>
#include <stdint.h>

#define LLAYERS 6
#define DMODEL  512
#define NH      8
#define HD      64
#define NVOCAB  10000
#define NB      32
#define NS      64
#define NNR     196
#define NTOK    (NB*NS)     // 2048
#define NCTOK   (NB*NNR)    // 6272
#define WSZ     ((size_t)DMODEL*DMODEL)
#define CSZ     ((size_t)NCTOK*DMODEL)

// ---------------- scratch (no cudaMalloc allowed) ----------------
__device__ float g_act[NTOK*DMODEL];
__device__ float g_q  [NTOK*DMODEL];
__device__ float g_k  [NTOK*DMODEL];
__device__ float g_v  [NTOK*DMODEL];
__device__ float g_ao [NTOK*DMODEL];
__device__ float g_kc [LLAYERS][CSZ];
__device__ float g_vc [LLAYERS][CSZ];
__device__ float g_gq [LLAYERS][NB*DMODEL];

// ---------------- embedding + positional encoding ----------------
__global__ void embed_kernel(const int* __restrict__ x, const float* __restrict__ emb,
                             float* __restrict__ out) {
    int t = blockIdx.x;
    int s = t % NS;
    int tok = x[t];
    for (int d = threadIdx.x; d < DMODEL; d += blockDim.x) {
        int j = d >> 1;
        float ang = (float)s * powf(10000.0f, -(2.0f*(float)j)/(float)DMODEL);
        float pe = (d & 1) ? cosf(ang) : sinf(ang);
        out[t*DMODEL + d] = emb[tok*DMODEL + d] + pe;
    }
}

// ---------------- SGEMM v2: 64x64 tile, 128 thr, 4x8/thread, double-buffered ----
__device__ __forceinline__ float4 ldg4_guard(const float* __restrict__ p, int n, int N, bool full) {
    if (full) return *(const float4*)p;
    float4 v;
    v.x = (n+0 < N) ? p[0] : 0.f;
    v.y = (n+1 < N) ? p[1] : 0.f;
    v.z = (n+2 < N) ? p[2] : 0.f;
    v.w = (n+3 < N) ? p[3] : 0.f;
    return v;
}

__device__ __forceinline__ void mm16(const float (*__restrict__ As16)[68],
                                     const float (*__restrict__ Bs16)[68],
                                     int rowA, int colB, float acc[4][8]) {
    #pragma unroll
    for (int kk = 0; kk < 16; kk++) {
        float4 a  = *(const float4*)&As16[kk][rowA];
        float4 p  = *(const float4*)&Bs16[kk][colB];
        float4 qq = *(const float4*)&Bs16[kk][colB+4];
        float av[4] = {a.x, a.y, a.z, a.w};
        float bv[8] = {p.x, p.y, p.z, p.w, qq.x, qq.y, qq.z, qq.w};
        #pragma unroll
        for (int i = 0; i < 4; i++)
            #pragma unroll
            for (int j = 0; j < 8; j++)
                acc[i][j] += av[i] * bv[j];
    }
}

__device__ __forceinline__ void gemm_tile(
    const float* __restrict__ A, const float* __restrict__ W, float* __restrict__ C,
    int M, int N, int K,
    const float* __restrict__ rowBias, const float* __restrict__ colBias)
{
    __shared__ float As[2][16][68];   // [buf][k][m]  (transposed)
    __shared__ float Bs[2][16][68];   // [buf][k][n]
    const int tid = threadIdx.x;
    const int w = tid >> 5, lane = tid & 31;
    const int wr = w >> 1, wc = w & 1;
    const int lr = lane >> 2, lc = lane & 3;
    const int m0 = blockIdx.y * 64, n0 = blockIdx.x * 64;
    const int rowA = wr*32 + lr*4;      // thread's 4 C rows
    const int colB = wc*32 + lc*8;      // thread's 8 C cols

    // staged global->smem mapping (2 float4 per thread per operand)
    const int q0 = tid*2, q1 = tid*2 + 1;
    const int ar0 = q0 >> 2, ac0 = (q0 & 3) * 4;
    const int ar1 = q1 >> 2, ac1 = (q1 & 3) * 4;
    const int br0 = q0 >> 4, bc0 = (q0 & 15) * 4;
    const int br1 = q1 >> 4, bc1 = (q1 & 15) * 4;
    const bool am0 = (m0 + ar0) < M, am1 = (m0 + ar1) < M;
    const int nc0 = n0 + bc0, nc1 = n0 + bc1;
    const bool bfull0 = (nc0 + 3) < N, bfull1 = (nc1 + 3) < N;
    const float* Ap0 = A + (size_t)(m0 + ar0) * K + ac0;
    const float* Ap1 = A + (size_t)(m0 + ar1) * K + ac1;
    const float* Bp0 = W + (size_t)br0 * N + nc0;
    const float* Bp1 = W + (size_t)br1 * N + nc1;

    float acc[4][8];
    #pragma unroll
    for (int i = 0; i < 4; i++)
        #pragma unroll
        for (int j = 0; j < 8; j++) acc[i][j] = 0.f;

    const float4 z4 = make_float4(0.f, 0.f, 0.f, 0.f);
    float4 a0 = am0 ? *(const float4*)Ap0 : z4;
    float4 a1 = am1 ? *(const float4*)Ap1 : z4;
    float4 b0 = ldg4_guard(Bp0, nc0, N, bfull0);
    float4 b1 = ldg4_guard(Bp1, nc1, N, bfull1);

    int buf = 0;
    As[0][ac0+0][ar0]=a0.x; As[0][ac0+1][ar0]=a0.y; As[0][ac0+2][ar0]=a0.z; As[0][ac0+3][ar0]=a0.w;
    As[0][ac1+0][ar1]=a1.x; As[0][ac1+1][ar1]=a1.y; As[0][ac1+2][ar1]=a1.z; As[0][ac1+3][ar1]=a1.w;
    *(float4*)&Bs[0][br0][bc0] = b0;
    *(float4*)&Bs[0][br1][bc1] = b1;
    __syncthreads();

    const int nk = K >> 4;
    for (int t = 1; t < nk; t++) {
        const size_t ka = (size_t)t * 16;
        a0 = am0 ? *(const float4*)(Ap0 + ka) : z4;
        a1 = am1 ? *(const float4*)(Ap1 + ka) : z4;
        b0 = ldg4_guard(Bp0 + ka * N, nc0, N, bfull0);
        b1 = ldg4_guard(Bp1 + ka * N, nc1, N, bfull1);

        mm16(As[buf], Bs[buf], rowA, colB, acc);

        buf ^= 1;
        As[buf][ac0+0][ar0]=a0.x; As[buf][ac0+1][ar0]=a0.y; As[buf][ac0+2][ar0]=a0.z; As[buf][ac0+3][ar0]=a0.w;
        As[buf][ac1+0][ar1]=a1.x; As[buf][ac1+1][ar1]=a1.y; As[buf][ac1+2][ar1]=a1.z; As[buf][ac1+3][ar1]=a1.w;
        *(float4*)&Bs[buf][br0][bc0] = b0;
        *(float4*)&Bs[buf][br1][bc1] = b1;
        __syncthreads();
    }
    mm16(As[buf], Bs[buf], rowA, colB, acc);

    // epilogue
    const int batch = m0 >> 6;   // rows within a 64-tile share the batch index
    #pragma unroll
    for (int i = 0; i < 4; i++) {
        int m = m0 + rowA + i;
        if (m >= M) break;
        float* Cp = C + (size_t)m * N;
        #pragma unroll
        for (int j = 0; j < 8; j++) {
            int n = n0 + colB + j;
            if (n >= N) continue;
            float v = acc[i][j];
            if (rowBias) v += rowBias[(size_t)batch * N + n];
            if (colBias) v += colBias[n];
            Cp[n] = v;
        }
    }
}

__global__ void __launch_bounds__(128) gemm1(
    const float* __restrict__ A, const float* __restrict__ W, float* __restrict__ C,
    int M, int N, int K, const float* __restrict__ rowBias, const float* __restrict__ colBias) {
    gemm_tile(A, W, C, M, N, K, rowBias, colBias);
}

__global__ void __launch_bounds__(128) gemm_qkv(
    const float* __restrict__ A,
    const float* __restrict__ W0, const float* __restrict__ W1, const float* __restrict__ W2,
    float* __restrict__ C0, float* __restrict__ C1, float* __restrict__ C2) {
    const float* W = (blockIdx.z == 0) ? W0 : (blockIdx.z == 1) ? W1 : W2;
    float*       C = (blockIdx.z == 0) ? C0 : (blockIdx.z == 1) ? C1 : C2;
    gemm_tile(A, W, C, NTOK, DMODEL, DMODEL, nullptr, nullptr);
}

__global__ void __launch_bounds__(128) gemm_cross(
    const float* __restrict__ Kin, const float* __restrict__ Vin,
    const float* __restrict__ Wk, const float* __restrict__ Wv,
    float* __restrict__ kc, float* __restrict__ vc) {
    const int z = blockIdx.z, l = z >> 1;
    const float* A = (z & 1) ? Vin : Kin;
    const float* W = ((z & 1) ? Wv : Wk) + (size_t)l * WSZ;
    float*       C = ((z & 1) ? vc : kc) + (size_t)l * CSZ;
    gemm_tile(A, W, C, NCTOK, DMODEL, DMODEL, nullptr, nullptr);
}

__global__ void __launch_bounds__(128) gemm_gq(
    const float* __restrict__ g, const float* __restrict__ Wg, float* __restrict__ gq) {
    const int l = blockIdx.z;
    gemm_tile(g, Wg + (size_t)l * WSZ, gq + (size_t)l * NB * DMODEL,
              NB, DMODEL, DMODEL, nullptr, nullptr);
}

// ---------------- fused attention (one CTA per (b,h)), online softmax ----------
#define ATTN_SMEM_FLOATS (3*64*65 + 8*64)
template<bool CAUSAL>
__global__ void attn_kernel(const float* __restrict__ Q, const float* __restrict__ Kb,
                            const float* __restrict__ Vb, float* __restrict__ O,
                            int skeys, int kvTokens) {
    extern __shared__ float sm[];
    float* Qs = sm;
    float* Ks = sm + 64*65;
    float* Vs = sm + 2*64*65;
    float* Ps = sm + 3*64*65;

    const int b = blockIdx.x / NH, h = blockIdx.x % NH;
    const int tid = threadIdx.x, w = tid >> 5, lane = tid & 31;

    for (int i = tid; i < 64*64; i += 256) {
        int r = i >> 6, c = i & 63;
        Qs[r*65 + c] = Q[(size_t)(b*NS + r)*DMODEL + h*HD + c];
    }
    float mrow[8], lrow[8], a0[8], a1[8];
    #pragma unroll
    for (int i = 0; i < 8; i++) { mrow[i] = -1e30f; lrow[i] = 0.f; a0[i] = 0.f; a1[i] = 0.f; }
    __syncthreads();

    const int nch = (skeys + 63) >> 6;
    for (int ch = 0; ch < nch; ch++) {
        const int kb = ch * 64;
        const int cnt = min(64, skeys - kb);
        for (int i = tid; i < 64*64; i += 256) {
            int r = i >> 6, c = i & 63;
            float kv = 0.f, vv = 0.f;
            if (r < cnt) {
                size_t off = (size_t)(b*kvTokens + kb + r)*DMODEL + h*HD + c;
                kv = Kb[off]; vv = Vb[off];
            }
            Ks[r*65 + c] = kv; Vs[r*65 + c] = vv;
        }
        __syncthreads();

        #pragma unroll
        for (int rr = 0; rr < 8; rr++) {
            const int r = w*8 + rr;
            const float* qr = &Qs[r*65];
            float d0 = 0.f, d1 = 0.f;
            #pragma unroll 8
            for (int d = 0; d < 64; d++) {
                float qd = qr[d];
                d0 += qd * Ks[lane*65 + d];
                d1 += qd * Ks[(lane+32)*65 + d];
            }
            float s0 = d0 * 0.125f, s1 = d1 * 0.125f;
            bool v0 = (lane      < cnt) && (!CAUSAL || (kb + lane)      <= r);
            bool v1 = (lane + 32 < cnt) && (!CAUSAL || (kb + lane + 32) <= r);
            if (!v0) s0 = -1e30f;
            if (!v1) s1 = -1e30f;
            float cm = fmaxf(s0, s1);
            #pragma unroll
            for (int o = 16; o > 0; o >>= 1) cm = fmaxf(cm, __shfl_xor_sync(0xffffffffu, cm, o));
            float nm = fmaxf(mrow[rr], cm);
            float corr = __expf(mrow[rr] - nm);
            float p0 = v0 ? __expf(s0 - nm) : 0.f;
            float p1 = v1 ? __expf(s1 - nm) : 0.f;
            float ps = p0 + p1;
            #pragma unroll
            for (int o = 16; o > 0; o >>= 1) ps += __shfl_xor_sync(0xffffffffu, ps, o);
            lrow[rr] = lrow[rr]*corr + ps;
            mrow[rr] = nm;
            a0[rr] *= corr; a1[rr] *= corr;
            Ps[w*64 + lane]      = p0;
            Ps[w*64 + lane + 32] = p1;
            __syncwarp();
            float acc0 = 0.f, acc1 = 0.f;
            #pragma unroll 8
            for (int k = 0; k < 64; k++) {
                float p = Ps[w*64 + k];
                acc0 += p * Vs[k*65 + lane];
                acc1 += p * Vs[k*65 + lane + 32];
            }
            a0[rr] += acc0; a1[rr] += acc1;
            __syncwarp();
        }
        __syncthreads();
    }
    #pragma unroll
    for (int rr = 0; rr < 8; rr++) {
        int r = w*8 + rr;
        float inv = 1.0f / lrow[rr];
        size_t o = (size_t)(b*NS + r)*DMODEL + h*HD;
        O[o + lane]      = a0[rr] * inv;
        O[o + lane + 32] = a1[rr] * inv;
    }
}

// ---------------- final row softmax over VOCAB (in-place on d_out) ------------
__global__ void softmax_kernel(float* __restrict__ out) {
    __shared__ float buf[NVOCAB];
    __shared__ float red[8];
    const int tid = threadIdx.x, w = tid >> 5, lane = tid & 31;
    float* p = out + (size_t)blockIdx.x * NVOCAB;

    float mx = -1e30f;
    for (int i = tid; i < NVOCAB; i += 256) { float v = p[i]; buf[i] = v; mx = fmaxf(mx, v); }
    #pragma unroll
    for (int o = 16; o > 0; o >>= 1) mx = fmaxf(mx, __shfl_xor_sync(0xffffffffu, mx, o));
    if (lane == 0) red[w] = mx;
    __syncthreads();
    mx = red[0];
    #pragma unroll
    for (int i = 1; i < 8; i++) mx = fmaxf(mx, red[i]);
    __syncthreads();

    float sum = 0.f;
    for (int i = tid; i < NVOCAB; i += 256) { float e = __expf(buf[i] - mx); buf[i] = e; sum += e; }
    #pragma unroll
    for (int o = 16; o > 0; o >>= 1) sum += __shfl_xor_sync(0xffffffffu, sum, o);
    if (lane == 0) red[w] = sum;
    __syncthreads();
    sum = 0.f;
    #pragma unroll
    for (int i = 0; i < 8; i++) sum += red[i];
    float inv = 1.0f / sum;
    for (int i = tid; i < NVOCAB; i += 256) p[i] = buf[i] * inv;
}

// ---------------- host launcher ----------------
extern "C" void kernel_launch(void* const* d_in, const int* in_sizes, int n_in,
                              void* d_out, int out_size) {
    const int*   x   = (const int*)  d_in[0];
    const float* Kin = (const float*)d_in[1];
    const float* Vin = (const float*)d_in[2];
    const float* g   = (const float*)d_in[3];
    int i = 4;
    if (i < n_in && in_sizes[i] == 1) i++;
    const float* emb  = (const float*)d_in[i++];
    const float* Wq_s = (const float*)d_in[i++];
    const float* Wk_s = (const float*)d_in[i++];
    const float* Wv_s = (const float*)d_in[i++];
    const float* Wo_s = (const float*)d_in[i++];
    const float* Wq_c = (const float*)d_in[i++];
    const float* Wg_c = (const float*)d_in[i++];
    const float* Wk_c = (const float*)d_in[i++];
    const float* Wv_c = (const float*)d_in[i++];
    const float* Wo_c = (const float*)d_in[i++];
    const float* Wf   = (const float*)d_in[i++];
    const float* bf   = (const float*)d_in[i++];

    float *act, *q, *k, *v, *ao, *kcB, *vcB, *gqB;
    cudaGetSymbolAddress((void**)&act, g_act);
    cudaGetSymbolAddress((void**)&q,   g_q);
    cudaGetSymbolAddress((void**)&k,   g_k);
    cudaGetSymbolAddress((void**)&v,   g_v);
    cudaGetSymbolAddress((void**)&ao,  g_ao);
    cudaGetSymbolAddress((void**)&kcB, g_kc);
    cudaGetSymbolAddress((void**)&vcB, g_vc);
    cudaGetSymbolAddress((void**)&gqB, g_gq);

    const int ATTN_SMEM = ATTN_SMEM_FLOATS * (int)sizeof(float);
    cudaFuncSetAttribute(attn_kernel<true>,  cudaFuncAttributeMaxDynamicSharedMemorySize, ATTN_SMEM);
    cudaFuncSetAttribute(attn_kernel<false>, cudaFuncAttributeMaxDynamicSharedMemorySize, ATTN_SMEM);

    embed_kernel<<<NTOK, 128>>>(x, emb, act);

    // all layer-independent projections up front (fills the chip, no deps)
    gemm_gq   <<<dim3(8, 1, LLAYERS), 128>>>(g, Wg_c, gqB);
    gemm_cross<<<dim3(8, NCTOK/64, 2*LLAYERS), 128>>>(Kin, Vin, Wk_c, Wv_c, kcB, vcB);

    for (int l = 0; l < LLAYERS; l++) {
        gemm_qkv<<<dim3(8, 32, 3), 128>>>(act, Wq_s + l*WSZ, Wk_s + l*WSZ, Wv_s + l*WSZ, q, k, v);
        attn_kernel<true><<<NB*NH, 256, ATTN_SMEM>>>(q, k, v, ao, NS, NS);
        gemm1<<<dim3(8, 32), 128>>>(ao, Wo_s + l*WSZ, act, NTOK, DMODEL, DMODEL, nullptr, nullptr);

        gemm1<<<dim3(8, 32), 128>>>(act, Wq_c + l*WSZ, q, NTOK, DMODEL, DMODEL,
                                    gqB + (size_t)l*NB*DMODEL, nullptr);
        attn_kernel<false><<<NB*NH, 256, ATTN_SMEM>>>(q, kcB + (size_t)l*CSZ, vcB + (size_t)l*CSZ,
                                                      ao, NNR, NNR);
        gemm1<<<dim3(8, 32), 128>>>(ao, Wo_c + l*WSZ, act, NTOK, DMODEL, DMODEL, nullptr, nullptr);
    }

    gemm1<<<dim3((NVOCAB + 63)/64, NTOK/64), 128>>>(act, Wf, (float*)d_out,
                                                    NTOK, NVOCAB, DMODEL, nullptr, bf);
    softmax_kernel<<<NTOK, 256>>>((float*)d_out);
}

// round 4
// speedup vs baseline: 1.7740x; 1.4909x over previous
#include <cuda_runtime.h>
#include <cuda_bf16.h>
#include <math.h>
#include <stdint.h>

typedef __nv_bfloat16 bf16;

#define LLAYERS 6
#define DMODEL  512
#define NH      8
#define HD      64
#define NVOCAB  10000
#define NB      32
#define NS      64
#define NNR     196
#define NTOK    (NB*NS)     // 2048
#define NCTOK   (NB*NNR)    // 6272
#define WSZ     ((size_t)DMODEL*DMODEL)
#define CSZ     ((size_t)NCTOK*DMODEL)

// ================= scratch =================
__device__ bf16  g_actH[NTOK*DMODEL], g_actL[NTOK*DMODEL];
__device__ float g_q[NTOK*DMODEL], g_k[NTOK*DMODEL], g_v[NTOK*DMODEL];
__device__ bf16  g_aoH[NTOK*DMODEL], g_aoL[NTOK*DMODEL];
__device__ float g_kc[LLAYERS][CSZ], g_vc[LLAYERS][CSZ];
__device__ float g_gq[LLAYERS][NB*DMODEL];
__device__ bf16  g_KinH[CSZ], g_KinL[CSZ], g_VinH[CSZ], g_VinL[CSZ];
__device__ bf16  g_gH[NB*DMODEL], g_gL[NB*DMODEL];
__device__ bf16  g_wTH[9*LLAYERS*WSZ], g_wTL[9*LLAYERS*WSZ];   // [N,K] transposed
__device__ bf16  g_wfTH[(size_t)NVOCAB*DMODEL], g_wfTL[(size_t)NVOCAB*DMODEL];

// ================= helpers =================
__device__ __forceinline__ uint32_t smem_to_u32(const void* p) {
    uint32_t a;
    asm("{ .reg .u64 t; cvta.to.shared.u64 t, %1; cvt.u32.u64 %0, t; }" : "=r"(a) : "l"(p));
    return a;
}
__device__ __forceinline__ void cp16(uint32_t dst, const void* src, bool p) {
    int sz = p ? 16 : 0;
    asm volatile("cp.async.cg.shared.global [%0], [%1], 16, %2;" :: "r"(dst), "l"(src), "r"(sz) : "memory");
}
#define CP_COMMIT() asm volatile("cp.async.commit_group;" ::: "memory")
#define CP_WAIT0()  asm volatile("cp.async.wait_group 0;" ::: "memory")

__device__ __forceinline__ void ldm4(uint32_t addr, uint32_t* r) {
    asm volatile("ldmatrix.sync.aligned.m8n8.x4.shared.b16 {%0,%1,%2,%3}, [%4];"
        : "=r"(r[0]), "=r"(r[1]), "=r"(r[2]), "=r"(r[3]) : "r"(addr));
}
__device__ __forceinline__ void mma16816(float* c, const uint32_t* a, uint32_t b0, uint32_t b1) {
    asm volatile("mma.sync.aligned.m16n8k16.row.col.f32.bf16.bf16.f32 "
        "{%0,%1,%2,%3}, {%4,%5,%6,%7}, {%8,%9}, {%0,%1,%2,%3};"
        : "+f"(c[0]), "+f"(c[1]), "+f"(c[2]), "+f"(c[3])
        : "r"(a[0]), "r"(a[1]), "r"(a[2]), "r"(a[3]), "r"(b0), "r"(b1));
}
__device__ __forceinline__ void split2(float v, bf16& h, bf16& l) {
    h = __float2bfloat16(v);
    l = __float2bfloat16(v - __bfloat162float(h));
}

// ================= conversion kernels =================
__global__ void split_kernel(const float* __restrict__ src, bf16* __restrict__ h,
                             bf16* __restrict__ l, int n) {
    int i = blockIdx.x * blockDim.x + threadIdx.x;
    if (i < n) { bf16 hh, ll; split2(src[i], hh, ll); h[i] = hh; l[i] = ll; }
}

// W [K,N] fp32 -> hi/lo [N,K] bf16 (transpose + split)
__global__ void wconv_kernel(const float* __restrict__ W, bf16* __restrict__ Th,
                             bf16* __restrict__ Tl, int Kdim, int Ndim) {
    __shared__ float t[32][33];
    const size_t msz = (size_t)Kdim * Ndim;
    const float* Wz = W + (size_t)blockIdx.z * msz;
    bf16* Thz = Th + (size_t)blockIdx.z * msz;
    bf16* Tlz = Tl + (size_t)blockIdx.z * msz;
    int n0 = blockIdx.x * 32, k0 = blockIdx.y * 32;
    int tx = threadIdx.x, ty = threadIdx.y;
    for (int r = ty; r < 32; r += 8) {
        int n = n0 + tx, k = k0 + r;
        t[r][tx] = (n < Ndim) ? Wz[(size_t)k * Ndim + n] : 0.f;
    }
    __syncthreads();
    for (int r = ty; r < 32; r += 8) {
        int n = n0 + r, k = k0 + tx;
        if (n < Ndim) {
            bf16 hh, ll; split2(t[tx][r], hh, ll);
            Thz[(size_t)n * Kdim + k] = hh;
            Tlz[(size_t)n * Kdim + k] = ll;
        }
    }
}

// ================= embedding + positional encoding =================
__global__ void embed_kernel(const int* __restrict__ x, const float* __restrict__ emb,
                             bf16* __restrict__ outH, bf16* __restrict__ outL) {
    int t = blockIdx.x;
    int s = t % NS;
    int tok = x[t];
    for (int d = threadIdx.x; d < DMODEL; d += blockDim.x) {
        int j = d >> 1;
        float ang = (float)s * powf(10000.0f, -(2.0f*(float)j)/(float)DMODEL);
        float pe = (d & 1) ? cosf(ang) : sinf(ang);
        float v = emb[tok*DMODEL + d] + pe;
        bf16 hh, ll; split2(v, hh, ll);
        outH[t*DMODEL + d] = hh; outL[t*DMODEL + d] = ll;
    }
}

// ================= split-bf16 HMMA GEMM =================
// C[M,N] = (Ah+Al)[M,512] @ (Bh+Bl)^T, B stored [N,512] (K-major rows).
// CTA tile 128x128, 8 warps (4m x 2n), warp tile 32x64, K-chunk 32.
#define STRIDE   40                       // bf16 elems per smem row (pad 32 -> 40)
#define TILE_B   (128*STRIDE*2)           // 10240 bytes per tile
#define BUF_B    (4*TILE_B)               // Ah,Al,Bh,Bl
#define GEMM_SMEM (2*BUF_B)               // double buffer = 81920

__device__ __forceinline__ void load_tiles(
    const bf16* __restrict__ Ah, const bf16* __restrict__ Al,
    const bf16* __restrict__ Bh, const bf16* __restrict__ Bl,
    int M, int N, int m0, int n0, int ch, uint32_t sbuf, int tid)
{
    const int row = tid >> 1;
    const int qd  = (tid & 1) * 2;                 // quad pair (2 x 16B)
    const uint32_t sof = sbuf + (uint32_t)(row*STRIDE + qd*8) * 2;
    // A tiles
    {
        bool ok = (m0 + row) < M;
        const bf16* pa = Ah + (size_t)(m0 + row) * 512 + ch*32 + qd*8;
        const bf16* pl = Al + (size_t)(m0 + row) * 512 + ch*32 + qd*8;
        cp16(sof,               pa,     ok);
        cp16(sof + 16,          pa + 8, ok);
        cp16(sof + TILE_B,      pl,     ok);
        cp16(sof + TILE_B + 16, pl + 8, ok);
    }
    // B tiles
    {
        bool ok = (n0 + row) < N;
        const bf16* pb = Bh + (size_t)(n0 + row) * 512 + ch*32 + qd*8;
        const bf16* pl = Bl + (size_t)(n0 + row) * 512 + ch*32 + qd*8;
        cp16(sof + 2*TILE_B,      pb,     ok);
        cp16(sof + 2*TILE_B + 16, pb + 8, ok);
        cp16(sof + 3*TILE_B,      pl,     ok);
        cp16(sof + 3*TILE_B + 16, pl + 8, ok);
    }
}

__device__ void gemm_core(const bf16* __restrict__ Ah, const bf16* __restrict__ Al,
                          const bf16* __restrict__ Bh, const bf16* __restrict__ Bl,
                          float* __restrict__ C, bf16* __restrict__ Ch, bf16* __restrict__ Cl,
                          int M, int N,
                          const float* __restrict__ rowBias, const float* __restrict__ colBias)
{
    extern __shared__ char smem[];
    const uint32_t sb = smem_to_u32(smem);
    const int tid = threadIdx.x, wid = tid >> 5, lane = tid & 31;
    const int wm = wid & 3, wn = wid >> 2;
    const int m0 = blockIdx.y * 128, n0 = blockIdx.x * 128;

    float acc[2][8][4];
    #pragma unroll
    for (int i = 0; i < 2; i++)
        #pragma unroll
        for (int j = 0; j < 8; j++)
            #pragma unroll
            for (int e = 0; e < 4; e++) acc[i][j][e] = 0.f;

    load_tiles(Ah, Al, Bh, Bl, M, N, m0, n0, 0, sb, tid);
    CP_COMMIT();

    int buf = 0;
    // per-warp ldmatrix lane addressing (element indices)
    const int aRow = (lane & 15);
    const int aCol = (lane >> 4) << 3;
    const int bRow = (lane & 7) + (((lane >> 4) & 1) << 3);
    const int bCol = ((lane >> 3) & 1) << 3;

    #pragma unroll 1
    for (int ch = 0; ch < 16; ch++) {
        CP_WAIT0();
        __syncthreads();
        if (ch + 1 < 16) {
            load_tiles(Ah, Al, Bh, Bl, M, N, m0, n0, ch + 1, sb + (buf ^ 1) * BUF_B, tid);
            CP_COMMIT();
        }
        const uint32_t sAh = sb + buf*BUF_B;
        const uint32_t sAl = sAh + TILE_B;
        const uint32_t sBh = sAh + 2*TILE_B;
        const uint32_t sBl = sAh + 3*TILE_B;

        #pragma unroll
        for (int k16 = 0; k16 < 32; k16 += 16) {
            uint32_t ah[8], al[8];
            {
                uint32_t a0 = (uint32_t)((wm*32 + aRow)*STRIDE + k16 + aCol) * 2;
                uint32_t a1 = (uint32_t)((wm*32 + 16 + aRow)*STRIDE + k16 + aCol) * 2;
                ldm4(sAh + a0, ah);  ldm4(sAh + a1, ah + 4);
                ldm4(sAl + a0, al);  ldm4(sAl + a1, al + 4);
            }
            #pragma unroll
            for (int half = 0; half < 2; half++) {
                #pragma unroll
                for (int pair = 0; pair < 2; pair++) {
                    const int nb = wn*64 + half*32 + pair*16;
                    const uint32_t boff = (uint32_t)((nb + bRow)*STRIDE + k16 + bCol) * 2;
                    uint32_t bh[4], bl[4];
                    ldm4(sBh + boff, bh);
                    ldm4(sBl + boff, bl);
                    const int na = half*4 + pair*2;
                    #pragma unroll
                    for (int mi = 0; mi < 2; mi++) {
                        mma16816(acc[mi][na],     ah + 4*mi, bh[0], bh[1]);
                        mma16816(acc[mi][na + 1], ah + 4*mi, bh[2], bh[3]);
                        mma16816(acc[mi][na],     ah + 4*mi, bl[0], bl[1]);
                        mma16816(acc[mi][na + 1], ah + 4*mi, bl[2], bl[3]);
                        mma16816(acc[mi][na],     al + 4*mi, bh[0], bh[1]);
                        mma16816(acc[mi][na + 1], al + 4*mi, bh[2], bh[3]);
                    }
                }
            }
        }
        buf ^= 1;
    }

    // epilogue
    const int r0 = m0 + wm*32 + (lane >> 2);
    const int c0 = n0 + wn*64 + (lane & 3) * 2;
    #pragma unroll
    for (int mi = 0; mi < 2; mi++) {
        #pragma unroll
        for (int na = 0; na < 8; na++) {
            const int col = c0 + na*8;
            #pragma unroll
            for (int e = 0; e < 4; e++) {
                const int r = r0 + mi*16 + ((e >> 1) << 3);
                const int c = col + (e & 1);
                if (r >= M || c >= N) continue;
                float v = acc[mi][na][e];
                if (rowBias) v += rowBias[(size_t)(r >> 6) * N + c];
                if (colBias) v += colBias[c];
                if (C) C[(size_t)r * N + c] = v;
                if (Ch) {
                    bf16 hh, ll; split2(v, hh, ll);
                    Ch[(size_t)r * N + c] = hh;
                    Cl[(size_t)r * N + c] = ll;
                }
            }
        }
    }
}

__global__ void __launch_bounds__(256) gemm_plain(
    const bf16* Ah, const bf16* Al, const bf16* Bh, const bf16* Bl,
    float* C, bf16* Ch, bf16* Cl, int M, int N,
    const float* rowBias, const float* colBias) {
    gemm_core(Ah, Al, Bh, Bl, C, Ch, Cl, M, N, rowBias, colBias);
}

__global__ void __launch_bounds__(256) gemm_qkv3(
    const bf16* Ah, const bf16* Al, const bf16* wTH, const bf16* wTL, int l,
    float* q, float* k, float* v) {
    const int z = blockIdx.z;
    const size_t off = ((size_t)z*LLAYERS + l) * WSZ;
    float* C = (z == 0) ? q : (z == 1) ? k : v;
    gemm_core(Ah, Al, wTH + off, wTL + off, C, nullptr, nullptr, NTOK, DMODEL, nullptr, nullptr);
}

__global__ void __launch_bounds__(256) gemm_cross12(
    const bf16* KinH, const bf16* KinL, const bf16* VinH, const bf16* VinL,
    const bf16* wTH, const bf16* wTL, float* kc, float* vc) {
    const int z = blockIdx.z, l = z >> 1, kv = z & 1;
    const size_t woff = ((size_t)(6 + kv)*LLAYERS + l) * WSZ;
    gemm_core(kv ? VinH : KinH, kv ? VinL : KinL, wTH + woff, wTL + woff,
              (kv ? vc : kc) + (size_t)l*CSZ, nullptr, nullptr, NCTOK, DMODEL, nullptr, nullptr);
}

__global__ void __launch_bounds__(256) gemm_gq6(
    const bf16* gH, const bf16* gL, const bf16* wTH, const bf16* wTL, float* gq) {
    const int l = blockIdx.z;
    const size_t woff = ((size_t)5*LLAYERS + l) * WSZ;
    gemm_core(gH, gL, wTH + woff, wTL + woff,
              gq + (size_t)l*NB*DMODEL, nullptr, nullptr, NB, DMODEL, nullptr, nullptr);
}

// ================= fused attention (fp32), writes hi/lo =================
#define ATTN_SMEM_FLOATS (3*64*65 + 8*64)
template<bool CAUSAL>
__global__ void attn_kernel(const float* __restrict__ Q, const float* __restrict__ Kb,
                            const float* __restrict__ Vb,
                            bf16* __restrict__ Oh, bf16* __restrict__ Ol,
                            int skeys, int kvTokens) {
    extern __shared__ float sm[];
    float* Qs = sm;
    float* Ks = sm + 64*65;
    float* Vs = sm + 2*64*65;
    float* Ps = sm + 3*64*65;

    const int b = blockIdx.x / NH, h = blockIdx.x % NH;
    const int tid = threadIdx.x, w = tid >> 5, lane = tid & 31;

    for (int i = tid; i < 64*64; i += 256) {
        int r = i >> 6, c = i & 63;
        Qs[r*65 + c] = Q[(size_t)(b*NS + r)*DMODEL + h*HD + c];
    }
    float mrow[8], lrow[8], a0[8], a1[8];
    #pragma unroll
    for (int i = 0; i < 8; i++) { mrow[i] = -1e30f; lrow[i] = 0.f; a0[i] = 0.f; a1[i] = 0.f; }
    __syncthreads();

    const int nch = (skeys + 63) >> 6;
    for (int ch = 0; ch < nch; ch++) {
        const int kb = ch * 64;
        const int cnt = min(64, skeys - kb);
        for (int i = tid; i < 64*64; i += 256) {
            int r = i >> 6, c = i & 63;
            float kv = 0.f, vv = 0.f;
            if (r < cnt) {
                size_t off = (size_t)(b*kvTokens + kb + r)*DMODEL + h*HD + c;
                kv = Kb[off]; vv = Vb[off];
            }
            Ks[r*65 + c] = kv; Vs[r*65 + c] = vv;
        }
        __syncthreads();

        #pragma unroll
        for (int rr = 0; rr < 8; rr++) {
            const int r = w*8 + rr;
            const float* qr = &Qs[r*65];
            float d0 = 0.f, d1 = 0.f;
            #pragma unroll 8
            for (int d = 0; d < 64; d++) {
                float qd = qr[d];
                d0 += qd * Ks[lane*65 + d];
                d1 += qd * Ks[(lane+32)*65 + d];
            }
            float s0 = d0 * 0.125f, s1 = d1 * 0.125f;
            bool v0 = (lane      < cnt) && (!CAUSAL || (kb + lane)      <= r);
            bool v1 = (lane + 32 < cnt) && (!CAUSAL || (kb + lane + 32) <= r);
            if (!v0) s0 = -1e30f;
            if (!v1) s1 = -1e30f;
            float cm = fmaxf(s0, s1);
            #pragma unroll
            for (int o = 16; o > 0; o >>= 1) cm = fmaxf(cm, __shfl_xor_sync(0xffffffffu, cm, o));
            float nm = fmaxf(mrow[rr], cm);
            float corr = __expf(mrow[rr] - nm);
            float p0 = v0 ? __expf(s0 - nm) : 0.f;
            float p1 = v1 ? __expf(s1 - nm) : 0.f;
            float ps = p0 + p1;
            #pragma unroll
            for (int o = 16; o > 0; o >>= 1) ps += __shfl_xor_sync(0xffffffffu, ps, o);
            lrow[rr] = lrow[rr]*corr + ps;
            mrow[rr] = nm;
            a0[rr] *= corr; a1[rr] *= corr;
            Ps[w*64 + lane]      = p0;
            Ps[w*64 + lane + 32] = p1;
            __syncwarp();
            float acc0 = 0.f, acc1 = 0.f;
            #pragma unroll 8
            for (int k = 0; k < 64; k++) {
                float p = Ps[w*64 + k];
                acc0 += p * Vs[k*65 + lane];
                acc1 += p * Vs[k*65 + lane + 32];
            }
            a0[rr] += acc0; a1[rr] += acc1;
            __syncwarp();
        }
        __syncthreads();
    }
    #pragma unroll
    for (int rr = 0; rr < 8; rr++) {
        int r = w*8 + rr;
        float inv = 1.0f / lrow[rr];
        size_t o = (size_t)(b*NS + r)*DMODEL + h*HD;
        float v0 = a0[rr] * inv, v1 = a1[rr] * inv;
        bf16 hh, ll;
        split2(v0, hh, ll); Oh[o + lane]      = hh; Ol[o + lane]      = ll;
        split2(v1, hh, ll); Oh[o + lane + 32] = hh; Ol[o + lane + 32] = ll;
    }
}

// ================= final row softmax over VOCAB (in-place) =================
__global__ void softmax_kernel(float* __restrict__ out) {
    __shared__ float buf[NVOCAB];
    __shared__ float red[8];
    const int tid = threadIdx.x, w = tid >> 5, lane = tid & 31;
    float* p = out + (size_t)blockIdx.x * NVOCAB;

    float mx = -1e30f;
    for (int i = tid; i < NVOCAB; i += 256) { float v = p[i]; buf[i] = v; mx = fmaxf(mx, v); }
    #pragma unroll
    for (int o = 16; o > 0; o >>= 1) mx = fmaxf(mx, __shfl_xor_sync(0xffffffffu, mx, o));
    if (lane == 0) red[w] = mx;
    __syncthreads();
    mx = red[0];
    #pragma unroll
    for (int i = 1; i < 8; i++) mx = fmaxf(mx, red[i]);
    __syncthreads();

    float sum = 0.f;
    for (int i = tid; i < NVOCAB; i += 256) { float e = __expf(buf[i] - mx); buf[i] = e; sum += e; }
    #pragma unroll
    for (int o = 16; o > 0; o >>= 1) sum += __shfl_xor_sync(0xffffffffu, sum, o);
    if (lane == 0) red[w] = sum;
    __syncthreads();
    sum = 0.f;
    #pragma unroll
    for (int i = 0; i < 8; i++) sum += red[i];
    float inv = 1.0f / sum;
    for (int i = tid; i < NVOCAB; i += 256) p[i] = buf[i] * inv;
}

// ================= host launcher =================
extern "C" void kernel_launch(void* const* d_in, const int* in_sizes, int n_in,
                              void* d_out, int out_size) {
    const int*   x   = (const int*)  d_in[0];
    const float* Kin = (const float*)d_in[1];
    const float* Vin = (const float*)d_in[2];
    const float* g   = (const float*)d_in[3];
    int i = 4;
    if (i < n_in && in_sizes[i] == 1) i++;
    const float* emb  = (const float*)d_in[i++];
    const float* Wq_s = (const float*)d_in[i++];
    const float* Wk_s = (const float*)d_in[i++];
    const float* Wv_s = (const float*)d_in[i++];
    const float* Wo_s = (const float*)d_in[i++];
    const float* Wq_c = (const float*)d_in[i++];
    const float* Wg_c = (const float*)d_in[i++];
    const float* Wk_c = (const float*)d_in[i++];
    const float* Wv_c = (const float*)d_in[i++];
    const float* Wo_c = (const float*)d_in[i++];
    const float* Wf   = (const float*)d_in[i++];
    const float* bf   = (const float*)d_in[i++];

    bf16 *actH, *actL, *aoH, *aoL, *KinH, *KinL, *VinH, *VinL, *gH, *gL, *wTH, *wTL, *wfTH, *wfTL;
    float *q, *k, *v, *kc, *vc, *gq;
    cudaGetSymbolAddress((void**)&actH, g_actH);  cudaGetSymbolAddress((void**)&actL, g_actL);
    cudaGetSymbolAddress((void**)&aoH,  g_aoH);   cudaGetSymbolAddress((void**)&aoL,  g_aoL);
    cudaGetSymbolAddress((void**)&KinH, g_KinH);  cudaGetSymbolAddress((void**)&KinL, g_KinL);
    cudaGetSymbolAddress((void**)&VinH, g_VinH);  cudaGetSymbolAddress((void**)&VinL, g_VinL);
    cudaGetSymbolAddress((void**)&gH,   g_gH);    cudaGetSymbolAddress((void**)&gL,   g_gL);
    cudaGetSymbolAddress((void**)&wTH,  g_wTH);   cudaGetSymbolAddress((void**)&wTL,  g_wTL);
    cudaGetSymbolAddress((void**)&wfTH, g_wfTH);  cudaGetSymbolAddress((void**)&wfTL, g_wfTL);
    cudaGetSymbolAddress((void**)&q,  g_q);  cudaGetSymbolAddress((void**)&k, g_k);
    cudaGetSymbolAddress((void**)&v,  g_v);
    cudaGetSymbolAddress((void**)&kc, g_kc); cudaGetSymbolAddress((void**)&vc, g_vc);
    cudaGetSymbolAddress((void**)&gq, g_gq);

    const int ATTN_SMEM = ATTN_SMEM_FLOATS * (int)sizeof(float);
    cudaFuncSetAttribute(attn_kernel<true>,  cudaFuncAttributeMaxDynamicSharedMemorySize, ATTN_SMEM);
    cudaFuncSetAttribute(attn_kernel<false>, cudaFuncAttributeMaxDynamicSharedMemorySize, ATTN_SMEM);
    cudaFuncSetAttribute(gemm_plain,   cudaFuncAttributeMaxDynamicSharedMemorySize, GEMM_SMEM);
    cudaFuncSetAttribute(gemm_qkv3,    cudaFuncAttributeMaxDynamicSharedMemorySize, GEMM_SMEM);
    cudaFuncSetAttribute(gemm_cross12, cudaFuncAttributeMaxDynamicSharedMemorySize, GEMM_SMEM);
    cudaFuncSetAttribute(gemm_gq6,     cudaFuncAttributeMaxDynamicSharedMemorySize, GEMM_SMEM);

    // weight transpose + split
    const float* wsrc[9] = {Wq_s, Wk_s, Wv_s, Wo_s, Wq_c, Wg_c, Wk_c, Wv_c, Wo_c};
    for (int m = 0; m < 9; m++)
        wconv_kernel<<<dim3(16, 16, LLAYERS), dim3(32, 8)>>>(
            wsrc[m], wTH + (size_t)m*LLAYERS*WSZ, wTL + (size_t)m*LLAYERS*WSZ, DMODEL, DMODEL);
    wconv_kernel<<<dim3((NVOCAB + 31)/32, 16, 1), dim3(32, 8)>>>(Wf, wfTH, wfTL, DMODEL, NVOCAB);

    // input splits
    split_kernel<<<((int)CSZ + 255)/256, 256>>>(Kin, KinH, KinL, (int)CSZ);
    split_kernel<<<((int)CSZ + 255)/256, 256>>>(Vin, VinH, VinL, (int)CSZ);
    split_kernel<<<(NB*DMODEL + 255)/256, 256>>>(g, gH, gL, NB*DMODEL);

    embed_kernel<<<NTOK, 128>>>(x, emb, actH, actL);

    // layer-independent projections
    gemm_gq6    <<<dim3(4, 1, LLAYERS), 256, GEMM_SMEM>>>(gH, gL, wTH, wTL, gq);
    gemm_cross12<<<dim3(4, NCTOK/128, 2*LLAYERS), 256, GEMM_SMEM>>>(
        KinH, KinL, VinH, VinL, wTH, wTL, kc, vc);

    for (int l = 0; l < LLAYERS; l++) {
        gemm_qkv3<<<dim3(4, NTOK/128, 3), 256, GEMM_SMEM>>>(actH, actL, wTH, wTL, l, q, k, v);
        attn_kernel<true><<<NB*NH, 256, ATTN_SMEM>>>(q, k, v, aoH, aoL, NS, NS);
        gemm_plain<<<dim3(4, NTOK/128), 256, GEMM_SMEM>>>(
            aoH, aoL, wTH + ((size_t)3*LLAYERS + l)*WSZ, wTL + ((size_t)3*LLAYERS + l)*WSZ,
            nullptr, actH, actL, NTOK, DMODEL, nullptr, nullptr);

        gemm_plain<<<dim3(4, NTOK/128), 256, GEMM_SMEM>>>(
            actH, actL, wTH + ((size_t)4*LLAYERS + l)*WSZ, wTL + ((size_t)4*LLAYERS + l)*WSZ,
            q, nullptr, nullptr, NTOK, DMODEL, gq + (size_t)l*NB*DMODEL, nullptr);
        attn_kernel<false><<<NB*NH, 256, ATTN_SMEM>>>(
            q, kc + (size_t)l*CSZ, vc + (size_t)l*CSZ, aoH, aoL, NNR, NNR);
        gemm_plain<<<dim3(4, NTOK/128), 256, GEMM_SMEM>>>(
            aoH, aoL, wTH + ((size_t)8*LLAYERS + l)*WSZ, wTL + ((size_t)8*LLAYERS + l)*WSZ,
            nullptr, actH, actL, NTOK, DMODEL, nullptr, nullptr);
    }

    gemm_plain<<<dim3((NVOCAB + 127)/128, NTOK/128), 256, GEMM_SMEM>>>(
        actH, actL, wfTH, wfTL, (float*)d_out, nullptr, nullptr, NTOK, NVOCAB, nullptr, bf);
    softmax_kernel<<<NTOK, 256>>>((float*)d_out);
}

// round 5
// speedup vs baseline: 1.9771x; 1.1145x over previous
#include <cuda_runtime.h>
#include <cuda_bf16.h>
#include <math.h>
#include <stdint.h>

typedef __nv_bfloat16 bf16;

#define LLAYERS 6
#define DMODEL  512
#define NH      8
#define HD      64
#define NVOCAB  10000
#define NB      32
#define NS      64
#define NNR     196
#define NTOK    (NB*NS)     // 2048
#define NCTOK   (NB*NNR)    // 6272
#define WSZ     ((size_t)DMODEL*DMODEL)
#define CSZ     ((size_t)NCTOK*DMODEL)

// ================= scratch =================
__device__ bf16  g_actH[NTOK*DMODEL], g_actL[NTOK*DMODEL];
__device__ float g_q[NTOK*DMODEL], g_k[NTOK*DMODEL], g_v[NTOK*DMODEL];
__device__ bf16  g_aoH[NTOK*DMODEL], g_aoL[NTOK*DMODEL];
__device__ float g_kc[LLAYERS][CSZ], g_vc[LLAYERS][CSZ];
__device__ float g_gq[LLAYERS][NB*DMODEL];
__device__ bf16  g_KinH[CSZ], g_KinL[CSZ], g_VinH[CSZ], g_VinL[CSZ];
__device__ bf16  g_gH[NB*DMODEL], g_gL[NB*DMODEL];
__device__ bf16  g_wTH[9*LLAYERS*WSZ], g_wTL[9*LLAYERS*WSZ];   // [N,K] transposed
__device__ bf16  g_wfTH[(size_t)NVOCAB*DMODEL], g_wfTL[(size_t)NVOCAB*DMODEL];

// ================= helpers =================
__device__ __forceinline__ uint32_t smem_to_u32(const void* p) {
    uint32_t a;
    asm("{ .reg .u64 t; cvta.to.shared.u64 t, %1; cvt.u32.u64 %0, t; }" : "=r"(a) : "l"(p));
    return a;
}
__device__ __forceinline__ void cp16(uint32_t dst, const void* src, bool p) {
    int sz = p ? 16 : 0;
    asm volatile("cp.async.cg.shared.global [%0], [%1], 16, %2;" :: "r"(dst), "l"(src), "r"(sz) : "memory");
}
#define CP_COMMIT() asm volatile("cp.async.commit_group;" ::: "memory")
#define CP_WAIT0()  asm volatile("cp.async.wait_group 0;" ::: "memory")

__device__ __forceinline__ void ldm4(uint32_t addr, uint32_t* r) {
    asm volatile("ldmatrix.sync.aligned.m8n8.x4.shared.b16 {%0,%1,%2,%3}, [%4];"
        : "=r"(r[0]), "=r"(r[1]), "=r"(r[2]), "=r"(r[3]) : "r"(addr));
}
__device__ __forceinline__ void mma16816(float* c, const uint32_t* a, uint32_t b0, uint32_t b1) {
    asm volatile("mma.sync.aligned.m16n8k16.row.col.f32.bf16.bf16.f32 "
        "{%0,%1,%2,%3}, {%4,%5,%6,%7}, {%8,%9}, {%0,%1,%2,%3};"
        : "+f"(c[0]), "+f"(c[1]), "+f"(c[2]), "+f"(c[3])
        : "r"(a[0]), "r"(a[1]), "r"(a[2]), "r"(a[3]), "r"(b0), "r"(b1));
}
__device__ __forceinline__ void split2(float v, bf16& h, bf16& l) {
    h = __float2bfloat16(v);
    l = __float2bfloat16(v - __bfloat162float(h));
}

// ================= conversion kernels =================
__global__ void split_kernel(const float* __restrict__ src, bf16* __restrict__ h,
                             bf16* __restrict__ l, int n) {
    int i = blockIdx.x * blockDim.x + threadIdx.x;
    if (i < n) { bf16 hh, ll; split2(src[i], hh, ll); h[i] = hh; l[i] = ll; }
}

struct WPtrs { const float* p[9]; };

// All 54 square weight matrices in one launch: z -> (matrix m, layer l)
__global__ void wconv_all_kernel(WPtrs wp, bf16* __restrict__ Th, bf16* __restrict__ Tl) {
    __shared__ float t[32][33];
    const int z = blockIdx.z, m = z / LLAYERS, l = z % LLAYERS;
    const float* Wz = wp.p[m] + (size_t)l * WSZ;
    bf16* Thz = Th + ((size_t)m*LLAYERS + l) * WSZ;
    bf16* Tlz = Tl + ((size_t)m*LLAYERS + l) * WSZ;
    int n0 = blockIdx.x * 32, k0 = blockIdx.y * 32;
    int tx = threadIdx.x, ty = threadIdx.y;
    for (int r = ty; r < 32; r += 8) {
        t[r][tx] = Wz[(size_t)(k0 + r) * DMODEL + n0 + tx];
    }
    __syncthreads();
    for (int r = ty; r < 32; r += 8) {
        bf16 hh, ll; split2(t[tx][r], hh, ll);
        Thz[(size_t)(n0 + r) * DMODEL + k0 + tx] = hh;
        Tlz[(size_t)(n0 + r) * DMODEL + k0 + tx] = ll;
    }
}

// Wf [K,N] fp32 -> hi/lo [N,K]
__global__ void wconv_kernel(const float* __restrict__ W, bf16* __restrict__ Th,
                             bf16* __restrict__ Tl, int Kdim, int Ndim) {
    __shared__ float t[32][33];
    int n0 = blockIdx.x * 32, k0 = blockIdx.y * 32;
    int tx = threadIdx.x, ty = threadIdx.y;
    for (int r = ty; r < 32; r += 8) {
        int n = n0 + tx;
        t[r][tx] = (n < Ndim) ? W[(size_t)(k0 + r) * Ndim + n] : 0.f;
    }
    __syncthreads();
    for (int r = ty; r < 32; r += 8) {
        int n = n0 + r;
        if (n < Ndim) {
            bf16 hh, ll; split2(t[tx][r], hh, ll);
            Th[(size_t)n * Kdim + k0 + tx] = hh;
            Tl[(size_t)n * Kdim + k0 + tx] = ll;
        }
    }
}

// ================= embedding + positional encoding =================
__global__ void embed_kernel(const int* __restrict__ x, const float* __restrict__ emb,
                             bf16* __restrict__ outH, bf16* __restrict__ outL) {
    int t = blockIdx.x;
    int s = t % NS;
    int tok = x[t];
    for (int d = threadIdx.x; d < DMODEL; d += blockDim.x) {
        int j = d >> 1;
        float ang = (float)s * powf(10000.0f, -(2.0f*(float)j)/(float)DMODEL);
        float pe = (d & 1) ? cosf(ang) : sinf(ang);
        float v = emb[tok*DMODEL + d] + pe;
        bf16 hh, ll; split2(v, hh, ll);
        outH[t*DMODEL + d] = hh; outL[t*DMODEL + d] = ll;
    }
}

// ================= split-bf16 HMMA GEMM =================
// C[M,N] = (Ah+Al)[M,512] @ (Bh+Bl)^T, B stored [N,512] K-major.
// CTA tile 128 x NT (NT = 64 or 128), 8 warps (4m x 2n), K-chunk 32.
#define STRIDE   40
#define TILE_A   (128*STRIDE*2)
template<int NT> struct TileCfg {
    static const int TB  = NT*STRIDE*2;
    static const int BUF = 2*TILE_A + 2*TB;
    static const int SMEM = 2*BUF;
    static const int NP  = NT/32;       // 16-col groups per warp
};

template<int NT>
__device__ __forceinline__ void load_tiles(
    const bf16* __restrict__ Ah, const bf16* __restrict__ Al,
    const bf16* __restrict__ Bh, const bf16* __restrict__ Bl,
    int M, int N, int m0, int n0, int ch, uint32_t sbuf, int tid)
{
    // A: 128 rows, 2 threads/row, 2 cp16 each, per tile
    {
        const int row = tid >> 1;
        const int qd  = (tid & 1) * 2;
        const uint32_t sof = sbuf + (uint32_t)(row*STRIDE + qd*8) * 2;
        bool ok = (m0 + row) < M;
        const bf16* pa = Ah + (size_t)(m0 + row) * 512 + ch*32 + qd*8;
        const bf16* pl = Al + (size_t)(m0 + row) * 512 + ch*32 + qd*8;
        cp16(sof,                pa,     ok);
        cp16(sof + 16,           pa + 8, ok);
        cp16(sof + TILE_A,       pl,     ok);
        cp16(sof + TILE_A + 16,  pl + 8, ok);
    }
    // B: NT rows
    if (NT == 128) {
        const int row = tid >> 1;
        const int qd  = (tid & 1) * 2;
        const uint32_t sof = sbuf + 2*TILE_A + (uint32_t)(row*STRIDE + qd*8) * 2;
        bool ok = (n0 + row) < N;
        const bf16* pb = Bh + (size_t)(n0 + row) * 512 + ch*32 + qd*8;
        const bf16* pl = Bl + (size_t)(n0 + row) * 512 + ch*32 + qd*8;
        cp16(sof,                         pb,     ok);
        cp16(sof + 16,                    pb + 8, ok);
        cp16(sof + TileCfg<NT>::TB,       pl,     ok);
        cp16(sof + TileCfg<NT>::TB + 16,  pl + 8, ok);
    } else {
        const int row = tid >> 2;            // 64 rows, 4 threads/row
        const int qd  = tid & 3;
        const uint32_t sof = sbuf + 2*TILE_A + (uint32_t)(row*STRIDE + qd*8) * 2;
        bool ok = (n0 + row) < N;
        cp16(sof,                        Bh + (size_t)(n0 + row) * 512 + ch*32 + qd*8, ok);
        cp16(sof + TileCfg<NT>::TB,      Bl + (size_t)(n0 + row) * 512 + ch*32 + qd*8, ok);
    }
}

template<int NT>
__device__ void gemm_core(const bf16* __restrict__ Ah, const bf16* __restrict__ Al,
                          const bf16* __restrict__ Bh, const bf16* __restrict__ Bl,
                          float* __restrict__ C, bf16* __restrict__ Ch, bf16* __restrict__ Cl,
                          int M, int N,
                          const float* __restrict__ rowBias, const float* __restrict__ colBias)
{
    extern __shared__ char smem[];
    const uint32_t sb = smem_to_u32(smem);
    const int tid = threadIdx.x, wid = tid >> 5, lane = tid & 31;
    const int wm = wid & 3, wn = wid >> 2;
    const int m0 = blockIdx.y * 128, n0 = blockIdx.x * NT;
    const int NP = TileCfg<NT>::NP;
    const int BUF = TileCfg<NT>::BUF;
    const int TB = TileCfg<NT>::TB;

    float acc[2][2*TileCfg<NT>::NP][4];
    #pragma unroll
    for (int i = 0; i < 2; i++)
        #pragma unroll
        for (int j = 0; j < 2*NP; j++)
            #pragma unroll
            for (int e = 0; e < 4; e++) acc[i][j][e] = 0.f;

    load_tiles<NT>(Ah, Al, Bh, Bl, M, N, m0, n0, 0, sb, tid);
    CP_COMMIT();

    int buf = 0;
    const int aRow = (lane & 15);
    const int aCol = (lane >> 4) << 3;
    const int bRow = (lane & 7) + (((lane >> 4) & 1) << 3);
    const int bCol = ((lane >> 3) & 1) << 3;

    #pragma unroll 1
    for (int ch = 0; ch < 16; ch++) {
        CP_WAIT0();
        __syncthreads();
        if (ch + 1 < 16) {
            load_tiles<NT>(Ah, Al, Bh, Bl, M, N, m0, n0, ch + 1, sb + (buf ^ 1) * BUF, tid);
            CP_COMMIT();
        }
        const uint32_t sAh = sb + buf*BUF;
        const uint32_t sAl = sAh + TILE_A;
        const uint32_t sBh = sAh + 2*TILE_A;
        const uint32_t sBl = sBh + TB;

        #pragma unroll
        for (int k16 = 0; k16 < 32; k16 += 16) {
            uint32_t ah[8], al[8];
            {
                uint32_t a0 = (uint32_t)((wm*32 + aRow)*STRIDE + k16 + aCol) * 2;
                uint32_t a1 = (uint32_t)((wm*32 + 16 + aRow)*STRIDE + k16 + aCol) * 2;
                ldm4(sAh + a0, ah);  ldm4(sAh + a1, ah + 4);
                ldm4(sAl + a0, al);  ldm4(sAl + a1, al + 4);
            }
            #pragma unroll
            for (int np = 0; np < NP; np++) {
                const int nb = wn*(NT/2) + np*16;
                const uint32_t boff = (uint32_t)((nb + bRow)*STRIDE + k16 + bCol) * 2;
                uint32_t bh[4], bl[4];
                ldm4(sBh + boff, bh);
                ldm4(sBl + boff, bl);
                const int na = np*2;
                #pragma unroll
                for (int mi = 0; mi < 2; mi++) {
                    mma16816(acc[mi][na],     ah + 4*mi, bh[0], bh[1]);
                    mma16816(acc[mi][na + 1], ah + 4*mi, bh[2], bh[3]);
                    mma16816(acc[mi][na],     ah + 4*mi, bl[0], bl[1]);
                    mma16816(acc[mi][na + 1], ah + 4*mi, bl[2], bl[3]);
                    mma16816(acc[mi][na],     al + 4*mi, bh[0], bh[1]);
                    mma16816(acc[mi][na + 1], al + 4*mi, bh[2], bh[3]);
                }
            }
        }
        buf ^= 1;
    }

    // epilogue
    const int r0 = m0 + wm*32 + (lane >> 2);
    const int c0 = n0 + wn*(NT/2) + (lane & 3) * 2;
    #pragma unroll
    for (int mi = 0; mi < 2; mi++) {
        #pragma unroll
        for (int na = 0; na < 2*NP; na++) {
            const int col = c0 + na*8;
            #pragma unroll
            for (int e = 0; e < 4; e++) {
                const int r = r0 + mi*16 + ((e >> 1) << 3);
                const int c = col + (e & 1);
                if (r >= M || c >= N) continue;
                float v = acc[mi][na][e];
                if (rowBias) v += rowBias[(size_t)(r >> 6) * N + c];
                if (colBias) v += colBias[c];
                if (C) C[(size_t)r * N + c] = v;
                if (Ch) {
                    bf16 hh, ll; split2(v, hh, ll);
                    Ch[(size_t)r * N + c] = hh;
                    Cl[(size_t)r * N + c] = ll;
                }
            }
        }
    }
}

__global__ void __launch_bounds__(256) gemm_plain64(
    const bf16* Ah, const bf16* Al, const bf16* Bh, const bf16* Bl,
    float* C, bf16* Ch, bf16* Cl, int M, int N,
    const float* rowBias, const float* colBias) {
    gemm_core<64>(Ah, Al, Bh, Bl, C, Ch, Cl, M, N, rowBias, colBias);
}

__global__ void __launch_bounds__(256) gemm_final128(
    const bf16* Ah, const bf16* Al, const bf16* Bh, const bf16* Bl,
    float* C, int M, int N, const float* colBias) {
    gemm_core<128>(Ah, Al, Bh, Bl, C, nullptr, nullptr, M, N, nullptr, colBias);
}

__global__ void __launch_bounds__(256) gemm_qkv3(
    const bf16* Ah, const bf16* Al, const bf16* wTH, const bf16* wTL, int l,
    float* q, float* k, float* v) {
    const int z = blockIdx.z;
    const size_t off = ((size_t)z*LLAYERS + l) * WSZ;
    float* C = (z == 0) ? q : (z == 1) ? k : v;
    gemm_core<64>(Ah, Al, wTH + off, wTL + off, C, nullptr, nullptr, NTOK, DMODEL, nullptr, nullptr);
}

__global__ void __launch_bounds__(256) gemm_cross12(
    const bf16* KinH, const bf16* KinL, const bf16* VinH, const bf16* VinL,
    const bf16* wTH, const bf16* wTL, float* kc, float* vc) {
    const int z = blockIdx.z, l = z >> 1, kv = z & 1;
    const size_t woff = ((size_t)(6 + kv)*LLAYERS + l) * WSZ;
    gemm_core<128>(kv ? VinH : KinH, kv ? VinL : KinL, wTH + woff, wTL + woff,
                   (kv ? vc : kc) + (size_t)l*CSZ, nullptr, nullptr, NCTOK, DMODEL, nullptr, nullptr);
}

__global__ void __launch_bounds__(256) gemm_gq6(
    const bf16* gH, const bf16* gL, const bf16* wTH, const bf16* wTL, float* gq) {
    const int l = blockIdx.z;
    const size_t woff = ((size_t)5*LLAYERS + l) * WSZ;
    gemm_core<64>(gH, gL, wTH + woff, wTL + woff,
                  gq + (size_t)l*NB*DMODEL, nullptr, nullptr, NB, DMODEL, nullptr, nullptr);
}

// ================= fused attention (fp32), writes hi/lo =================
#define ATTN_SMEM_FLOATS (3*64*65 + 8*64)
template<bool CAUSAL>
__global__ void attn_kernel(const float* __restrict__ Q, const float* __restrict__ Kb,
                            const float* __restrict__ Vb,
                            bf16* __restrict__ Oh, bf16* __restrict__ Ol,
                            int skeys, int kvTokens) {
    extern __shared__ float sm[];
    float* Qs = sm;
    float* Ks = sm + 64*65;
    float* Vs = sm + 2*64*65;
    float* Ps = sm + 3*64*65;

    const int b = blockIdx.x / NH, h = blockIdx.x % NH;
    const int tid = threadIdx.x, w = tid >> 5, lane = tid & 31;

    for (int i = tid; i < 64*64; i += 256) {
        int r = i >> 6, c = i & 63;
        Qs[r*65 + c] = Q[(size_t)(b*NS + r)*DMODEL + h*HD + c];
    }
    float mrow[8], lrow[8], a0[8], a1[8];
    #pragma unroll
    for (int i = 0; i < 8; i++) { mrow[i] = -1e30f; lrow[i] = 0.f; a0[i] = 0.f; a1[i] = 0.f; }
    __syncthreads();

    const int nch = (skeys + 63) >> 6;
    for (int ch = 0; ch < nch; ch++) {
        const int kb = ch * 64;
        const int cnt = min(64, skeys - kb);
        for (int i = tid; i < 64*64; i += 256) {
            int r = i >> 6, c = i & 63;
            float kv = 0.f, vv = 0.f;
            if (r < cnt) {
                size_t off = (size_t)(b*kvTokens + kb + r)*DMODEL + h*HD + c;
                kv = Kb[off]; vv = Vb[off];
            }
            Ks[r*65 + c] = kv; Vs[r*65 + c] = vv;
        }
        __syncthreads();

        #pragma unroll
        for (int rr = 0; rr < 8; rr++) {
            const int r = w*8 + rr;
            const float* qr = &Qs[r*65];
            float d0 = 0.f, d1 = 0.f;
            #pragma unroll 8
            for (int d = 0; d < 64; d++) {
                float qd = qr[d];
                d0 += qd * Ks[lane*65 + d];
                d1 += qd * Ks[(lane+32)*65 + d];
            }
            float s0 = d0 * 0.125f, s1 = d1 * 0.125f;
            bool v0 = (lane      < cnt) && (!CAUSAL || (kb + lane)      <= r);
            bool v1 = (lane + 32 < cnt) && (!CAUSAL || (kb + lane + 32) <= r);
            if (!v0) s0 = -1e30f;
            if (!v1) s1 = -1e30f;
            float cm = fmaxf(s0, s1);
            #pragma unroll
            for (int o = 16; o > 0; o >>= 1) cm = fmaxf(cm, __shfl_xor_sync(0xffffffffu, cm, o));
            float nm = fmaxf(mrow[rr], cm);
            float corr = __expf(mrow[rr] - nm);
            float p0 = v0 ? __expf(s0 - nm) : 0.f;
            float p1 = v1 ? __expf(s1 - nm) : 0.f;
            float ps = p0 + p1;
            #pragma unroll
            for (int o = 16; o > 0; o >>= 1) ps += __shfl_xor_sync(0xffffffffu, ps, o);
            lrow[rr] = lrow[rr]*corr + ps;
            mrow[rr] = nm;
            a0[rr] *= corr; a1[rr] *= corr;
            Ps[w*64 + lane]      = p0;
            Ps[w*64 + lane + 32] = p1;
            __syncwarp();
            float acc0 = 0.f, acc1 = 0.f;
            #pragma unroll 8
            for (int k = 0; k < 64; k++) {
                float p = Ps[w*64 + k];
                acc0 += p * Vs[k*65 + lane];
                acc1 += p * Vs[k*65 + lane + 32];
            }
            a0[rr] += acc0; a1[rr] += acc1;
            __syncwarp();
        }
        __syncthreads();
    }
    #pragma unroll
    for (int rr = 0; rr < 8; rr++) {
        int r = w*8 + rr;
        float inv = 1.0f / lrow[rr];
        size_t o = (size_t)(b*NS + r)*DMODEL + h*HD;
        float v0 = a0[rr] * inv, v1 = a1[rr] * inv;
        bf16 hh, ll;
        split2(v0, hh, ll); Oh[o + lane]      = hh; Ol[o + lane]      = ll;
        split2(v1, hh, ll); Oh[o + lane + 32] = hh; Ol[o + lane + 32] = ll;
    }
}

// ================= final row softmax over VOCAB (in-place) =================
__global__ void softmax_kernel(float* __restrict__ out) {
    __shared__ float buf[NVOCAB];
    __shared__ float red[8];
    const int tid = threadIdx.x, w = tid >> 5, lane = tid & 31;
    float* p = out + (size_t)blockIdx.x * NVOCAB;

    float mx = -1e30f;
    for (int i = tid; i < NVOCAB; i += 256) { float v = p[i]; buf[i] = v; mx = fmaxf(mx, v); }
    #pragma unroll
    for (int o = 16; o > 0; o >>= 1) mx = fmaxf(mx, __shfl_xor_sync(0xffffffffu, mx, o));
    if (lane == 0) red[w] = mx;
    __syncthreads();
    mx = red[0];
    #pragma unroll
    for (int i = 1; i < 8; i++) mx = fmaxf(mx, red[i]);
    __syncthreads();

    float sum = 0.f;
    for (int i = tid; i < NVOCAB; i += 256) { float e = __expf(buf[i] - mx); buf[i] = e; sum += e; }
    #pragma unroll
    for (int o = 16; o > 0; o >>= 1) sum += __shfl_xor_sync(0xffffffffu, sum, o);
    if (lane == 0) red[w] = sum;
    __syncthreads();
    sum = 0.f;
    #pragma unroll
    for (int i = 0; i < 8; i++) sum += red[i];
    float inv = 1.0f / sum;
    for (int i = tid; i < NVOCAB; i += 256) p[i] = buf[i] * inv;
}

// ================= host launcher =================
extern "C" void kernel_launch(void* const* d_in, const int* in_sizes, int n_in,
                              void* d_out, int out_size) {
    const int*   x   = (const int*)  d_in[0];
    const float* Kin = (const float*)d_in[1];
    const float* Vin = (const float*)d_in[2];
    const float* g   = (const float*)d_in[3];
    int i = 4;
    if (i < n_in && in_sizes[i] == 1) i++;
    const float* emb  = (const float*)d_in[i++];
    const float* Wq_s = (const float*)d_in[i++];
    const float* Wk_s = (const float*)d_in[i++];
    const float* Wv_s = (const float*)d_in[i++];
    const float* Wo_s = (const float*)d_in[i++];
    const float* Wq_c = (const float*)d_in[i++];
    const float* Wg_c = (const float*)d_in[i++];
    const float* Wk_c = (const float*)d_in[i++];
    const float* Wv_c = (const float*)d_in[i++];
    const float* Wo_c = (const float*)d_in[i++];
    const float* Wf   = (const float*)d_in[i++];
    const float* bf   = (const float*)d_in[i++];

    bf16 *actH, *actL, *aoH, *aoL, *KinH, *KinL, *VinH, *VinL, *gH, *gL, *wTH, *wTL, *wfTH, *wfTL;
    float *q, *k, *v, *kc, *vc, *gq;
    cudaGetSymbolAddress((void**)&actH, g_actH);  cudaGetSymbolAddress((void**)&actL, g_actL);
    cudaGetSymbolAddress((void**)&aoH,  g_aoH);   cudaGetSymbolAddress((void**)&aoL,  g_aoL);
    cudaGetSymbolAddress((void**)&KinH, g_KinH);  cudaGetSymbolAddress((void**)&KinL, g_KinL);
    cudaGetSymbolAddress((void**)&VinH, g_VinH);  cudaGetSymbolAddress((void**)&VinL, g_VinL);
    cudaGetSymbolAddress((void**)&gH,   g_gH);    cudaGetSymbolAddress((void**)&gL,   g_gL);
    cudaGetSymbolAddress((void**)&wTH,  g_wTH);   cudaGetSymbolAddress((void**)&wTL,  g_wTL);
    cudaGetSymbolAddress((void**)&wfTH, g_wfTH);  cudaGetSymbolAddress((void**)&wfTL, g_wfTL);
    cudaGetSymbolAddress((void**)&q,  g_q);  cudaGetSymbolAddress((void**)&k, g_k);
    cudaGetSymbolAddress((void**)&v,  g_v);
    cudaGetSymbolAddress((void**)&kc, g_kc); cudaGetSymbolAddress((void**)&vc, g_vc);
    cudaGetSymbolAddress((void**)&gq, g_gq);

    const int ATTN_SMEM = ATTN_SMEM_FLOATS * (int)sizeof(float);
    cudaFuncSetAttribute(attn_kernel<true>,  cudaFuncAttributeMaxDynamicSharedMemorySize, ATTN_SMEM);
    cudaFuncSetAttribute(attn_kernel<false>, cudaFuncAttributeMaxDynamicSharedMemorySize, ATTN_SMEM);
    cudaFuncSetAttribute(gemm_plain64,  cudaFuncAttributeMaxDynamicSharedMemorySize, TileCfg<64>::SMEM);
    cudaFuncSetAttribute(gemm_qkv3,     cudaFuncAttributeMaxDynamicSharedMemorySize, TileCfg<64>::SMEM);
    cudaFuncSetAttribute(gemm_gq6,      cudaFuncAttributeMaxDynamicSharedMemorySize, TileCfg<64>::SMEM);
    cudaFuncSetAttribute(gemm_cross12,  cudaFuncAttributeMaxDynamicSharedMemorySize, TileCfg<128>::SMEM);
    cudaFuncSetAttribute(gemm_final128, cudaFuncAttributeMaxDynamicSharedMemorySize, TileCfg<128>::SMEM);

    // weight transpose + split: one launch for the 54 square matrices, one for Wf
    WPtrs wp;
    wp.p[0]=Wq_s; wp.p[1]=Wk_s; wp.p[2]=Wv_s; wp.p[3]=Wo_s; wp.p[4]=Wq_c;
    wp.p[5]=Wg_c; wp.p[6]=Wk_c; wp.p[7]=Wv_c; wp.p[8]=Wo_c;
    wconv_all_kernel<<<dim3(16, 16, 9*LLAYERS), dim3(32, 8)>>>(wp, wTH, wTL);
    wconv_kernel<<<dim3((NVOCAB + 31)/32, 16, 1), dim3(32, 8)>>>(Wf, wfTH, wfTL, DMODEL, NVOCAB);

    // input splits
    split_kernel<<<((int)CSZ + 255)/256, 256>>>(Kin, KinH, KinL, (int)CSZ);
    split_kernel<<<((int)CSZ + 255)/256, 256>>>(Vin, VinH, VinL, (int)CSZ);
    split_kernel<<<(NB*DMODEL + 255)/256, 256>>>(g, gH, gL, NB*DMODEL);

    embed_kernel<<<NTOK, 128>>>(x, emb, actH, actL);

    // layer-independent projections
    gemm_gq6    <<<dim3(8, 1, LLAYERS), 256, TileCfg<64>::SMEM>>>(gH, gL, wTH, wTL, gq);
    gemm_cross12<<<dim3(4, NCTOK/128, 2*LLAYERS), 256, TileCfg<128>::SMEM>>>(
        KinH, KinL, VinH, VinL, wTH, wTL, kc, vc);

    for (int l = 0; l < LLAYERS; l++) {
        gemm_qkv3<<<dim3(8, NTOK/128, 3), 256, TileCfg<64>::SMEM>>>(actH, actL, wTH, wTL, l, q, k, v);
        attn_kernel<true><<<NB*NH, 256, ATTN_SMEM>>>(q, k, v, aoH, aoL, NS, NS);
        gemm_plain64<<<dim3(8, NTOK/128), 256, TileCfg<64>::SMEM>>>(
            aoH, aoL, wTH + ((size_t)3*LLAYERS + l)*WSZ, wTL + ((size_t)3*LLAYERS + l)*WSZ,
            nullptr, actH, actL, NTOK, DMODEL, nullptr, nullptr);

        gemm_plain64<<<dim3(8, NTOK/128), 256, TileCfg<64>::SMEM>>>(
            actH, actL, wTH + ((size_t)4*LLAYERS + l)*WSZ, wTL + ((size_t)4*LLAYERS + l)*WSZ,
            q, nullptr, nullptr, NTOK, DMODEL, gq + (size_t)l*NB*DMODEL, nullptr);
        attn_kernel<false><<<NB*NH, 256, ATTN_SMEM>>>(
            q, kc + (size_t)l*CSZ, vc + (size_t)l*CSZ, aoH, aoL, NNR, NNR);
        gemm_plain64<<<dim3(8, NTOK/128), 256, TileCfg<64>::SMEM>>>(
            aoH, aoL, wTH + ((size_t)8*LLAYERS + l)*WSZ, wTL + ((size_t)8*LLAYERS + l)*WSZ,
            nullptr, actH, actL, NTOK, DMODEL, nullptr, nullptr);
    }

    gemm_final128<<<dim3((NVOCAB + 127)/128, NTOK/128), 256, TileCfg<128>::SMEM>>>(
        actH, actL, wfTH, wfTL, (float*)d_out, NTOK, NVOCAB, bf);
    softmax_kernel<<<NTOK, 256>>>((float*)d_out);
}

// round 6
// speedup vs baseline: 2.3671x; 1.1972x over previous
#include <cuda_runtime.h>
#include <cuda_bf16.h>
#include <math.h>
#include <stdint.h>

typedef __nv_bfloat16 bf16;

#define LLAYERS 6
#define DMODEL  512
#define NH      8
#define HD      64
#define NVOCAB  10000
#define NB      32
#define NS      64
#define NNR     196
#define NTOK    (NB*NS)     // 2048
#define NCTOK   (NB*NNR)    // 6272
#define WSZ     ((size_t)DMODEL*DMODEL)
#define CSZ     ((size_t)NCTOK*DMODEL)

// ================= scratch =================
__device__ bf16  g_actH[NTOK*DMODEL], g_actL[NTOK*DMODEL];
__device__ float g_q[NTOK*DMODEL], g_k[NTOK*DMODEL], g_v[NTOK*DMODEL];
__device__ bf16  g_aoH[NTOK*DMODEL], g_aoL[NTOK*DMODEL];
__device__ float g_kc[LLAYERS][CSZ], g_vc[LLAYERS][CSZ];
__device__ float g_gq[LLAYERS][NB*DMODEL];
__device__ bf16  g_KinH[CSZ], g_KinL[CSZ], g_VinH[CSZ], g_VinL[CSZ];
__device__ bf16  g_gH[NB*DMODEL], g_gL[NB*DMODEL];
__device__ bf16  g_wTH[9*LLAYERS*WSZ], g_wTL[9*LLAYERS*WSZ];   // [N,K] transposed
__device__ bf16  g_wfTH[(size_t)NVOCAB*DMODEL], g_wfTL[(size_t)NVOCAB*DMODEL];

// ================= helpers =================
__device__ __forceinline__ uint32_t smem_to_u32(const void* p) {
    uint32_t a;
    asm("{ .reg .u64 t; cvta.to.shared.u64 t, %1; cvt.u32.u64 %0, t; }" : "=r"(a) : "l"(p));
    return a;
}
__device__ __forceinline__ void cp16(uint32_t dst, const void* src, bool p) {
    int sz = p ? 16 : 0;
    asm volatile("cp.async.cg.shared.global [%0], [%1], 16, %2;" :: "r"(dst), "l"(src), "r"(sz) : "memory");
}
#define CP_COMMIT() asm volatile("cp.async.commit_group;" ::: "memory")
#define CP_WAIT0()  asm volatile("cp.async.wait_group 0;" ::: "memory")
#define CP_WAIT1()  asm volatile("cp.async.wait_group 1;" ::: "memory")

__device__ __forceinline__ void ldm4(uint32_t addr, uint32_t* r) {
    asm volatile("ldmatrix.sync.aligned.m8n8.x4.shared.b16 {%0,%1,%2,%3}, [%4];"
        : "=r"(r[0]), "=r"(r[1]), "=r"(r[2]), "=r"(r[3]) : "r"(addr));
}
__device__ __forceinline__ void mma16816(float* c, const uint32_t* a, uint32_t b0, uint32_t b1) {
    asm volatile("mma.sync.aligned.m16n8k16.row.col.f32.bf16.bf16.f32 "
        "{%0,%1,%2,%3}, {%4,%5,%6,%7}, {%8,%9}, {%0,%1,%2,%3};"
        : "+f"(c[0]), "+f"(c[1]), "+f"(c[2]), "+f"(c[3])
        : "r"(a[0]), "r"(a[1]), "r"(a[2]), "r"(a[3]), "r"(b0), "r"(b1));
}
__device__ __forceinline__ void split2(float v, bf16& h, bf16& l) {
    h = __float2bfloat16(v);
    l = __float2bfloat16(v - __bfloat162float(h));
}

// ================= conversion kernels =================
union BPack { bf16 b[4]; uint2 u; };

__global__ void split_kernel(const float* __restrict__ src, bf16* __restrict__ h,
                             bf16* __restrict__ l, int n) {
    int i = (blockIdx.x * blockDim.x + threadIdx.x) * 4;
    if (i < n) {
        float4 v = *(const float4*)(src + i);
        BPack ph, pl;
        split2(v.x, ph.b[0], pl.b[0]);
        split2(v.y, ph.b[1], pl.b[1]);
        split2(v.z, ph.b[2], pl.b[2]);
        split2(v.w, ph.b[3], pl.b[3]);
        *(uint2*)(h + i) = ph.u;
        *(uint2*)(l + i) = pl.u;
    }
}

struct WPtrs { const float* p[9]; };

// All 54 square weight matrices in one launch: z -> (matrix m, layer l)
__global__ void wconv_all_kernel(WPtrs wp, bf16* __restrict__ Th, bf16* __restrict__ Tl) {
    __shared__ float t[32][33];
    const int z = blockIdx.z, m = z / LLAYERS, l = z % LLAYERS;
    const float* Wz = wp.p[m] + (size_t)l * WSZ;
    bf16* Thz = Th + ((size_t)m*LLAYERS + l) * WSZ;
    bf16* Tlz = Tl + ((size_t)m*LLAYERS + l) * WSZ;
    int n0 = blockIdx.x * 32, k0 = blockIdx.y * 32;
    int tx = threadIdx.x, ty = threadIdx.y;
    for (int r = ty; r < 32; r += 8) {
        t[r][tx] = Wz[(size_t)(k0 + r) * DMODEL + n0 + tx];
    }
    __syncthreads();
    for (int r = ty; r < 32; r += 8) {
        bf16 hh, ll; split2(t[tx][r], hh, ll);
        Thz[(size_t)(n0 + r) * DMODEL + k0 + tx] = hh;
        Tlz[(size_t)(n0 + r) * DMODEL + k0 + tx] = ll;
    }
}

// Wf [K,N] fp32 -> hi/lo [N,K]
__global__ void wconv_kernel(const float* __restrict__ W, bf16* __restrict__ Th,
                             bf16* __restrict__ Tl, int Kdim, int Ndim) {
    __shared__ float t[32][33];
    int n0 = blockIdx.x * 32, k0 = blockIdx.y * 32;
    int tx = threadIdx.x, ty = threadIdx.y;
    for (int r = ty; r < 32; r += 8) {
        int n = n0 + tx;
        t[r][tx] = (n < Ndim) ? W[(size_t)(k0 + r) * Ndim + n] : 0.f;
    }
    __syncthreads();
    for (int r = ty; r < 32; r += 8) {
        int n = n0 + r;
        if (n < Ndim) {
            bf16 hh, ll; split2(t[tx][r], hh, ll);
            Th[(size_t)n * Kdim + k0 + tx] = hh;
            Tl[(size_t)n * Kdim + k0 + tx] = ll;
        }
    }
}

// ================= embedding + positional encoding =================
__global__ void embed_kernel(const int* __restrict__ x, const float* __restrict__ emb,
                             bf16* __restrict__ outH, bf16* __restrict__ outL) {
    int t = blockIdx.x;
    int s = t % NS;
    int tok = x[t];
    for (int d = threadIdx.x; d < DMODEL; d += blockDim.x) {
        int j = d >> 1;
        float ang = (float)s * powf(10000.0f, -(2.0f*(float)j)/(float)DMODEL);
        float pe = (d & 1) ? cosf(ang) : sinf(ang);
        float v = emb[tok*DMODEL + d] + pe;
        bf16 hh, ll; split2(v, hh, ll);
        outH[t*DMODEL + d] = hh; outL[t*DMODEL + d] = ll;
    }
}

// ================= split-bf16 HMMA GEMM (3-stage pipeline) =================
#define STRIDE   40
#define TILE_A   (128*STRIDE*2)
template<int NT> struct TileCfg {
    static const int TB  = NT*STRIDE*2;
    static const int BUF = 2*TILE_A + 2*TB;
    static const int SMEM = 3*BUF;
    static const int NP  = NT/32;
};

template<int NT>
__device__ __forceinline__ void load_tiles(
    const bf16* __restrict__ Ah, const bf16* __restrict__ Al,
    const bf16* __restrict__ Bh, const bf16* __restrict__ Bl,
    int M, int N, int m0, int n0, int ch, uint32_t sbuf, int tid)
{
    {
        const int row = tid >> 1;
        const int qd  = (tid & 1) * 2;
        const uint32_t sof = sbuf + (uint32_t)(row*STRIDE + qd*8) * 2;
        bool ok = (m0 + row) < M;
        const bf16* pa = Ah + (size_t)(m0 + row) * 512 + ch*32 + qd*8;
        const bf16* pl = Al + (size_t)(m0 + row) * 512 + ch*32 + qd*8;
        cp16(sof,                pa,     ok);
        cp16(sof + 16,           pa + 8, ok);
        cp16(sof + TILE_A,       pl,     ok);
        cp16(sof + TILE_A + 16,  pl + 8, ok);
    }
    if (NT == 128) {
        const int row = tid >> 1;
        const int qd  = (tid & 1) * 2;
        const uint32_t sof = sbuf + 2*TILE_A + (uint32_t)(row*STRIDE + qd*8) * 2;
        bool ok = (n0 + row) < N;
        const bf16* pb = Bh + (size_t)(n0 + row) * 512 + ch*32 + qd*8;
        const bf16* pl = Bl + (size_t)(n0 + row) * 512 + ch*32 + qd*8;
        cp16(sof,                         pb,     ok);
        cp16(sof + 16,                    pb + 8, ok);
        cp16(sof + TileCfg<NT>::TB,       pl,     ok);
        cp16(sof + TileCfg<NT>::TB + 16,  pl + 8, ok);
    } else {
        const int row = tid >> 2;
        const int qd  = tid & 3;
        const uint32_t sof = sbuf + 2*TILE_A + (uint32_t)(row*STRIDE + qd*8) * 2;
        bool ok = (n0 + row) < N;
        cp16(sof,                        Bh + (size_t)(n0 + row) * 512 + ch*32 + qd*8, ok);
        cp16(sof + TileCfg<NT>::TB,      Bl + (size_t)(n0 + row) * 512 + ch*32 + qd*8, ok);
    }
}

template<int NT>
__device__ void gemm_core(const bf16* __restrict__ Ah, const bf16* __restrict__ Al,
                          const bf16* __restrict__ Bh, const bf16* __restrict__ Bl,
                          float* __restrict__ C, bf16* __restrict__ Ch, bf16* __restrict__ Cl,
                          int M, int N,
                          const float* __restrict__ rowBias, const float* __restrict__ colBias)
{
    extern __shared__ char smem[];
    const uint32_t sb = smem_to_u32(smem);
    const int tid = threadIdx.x, wid = tid >> 5, lane = tid & 31;
    const int wm = wid & 3, wn = wid >> 2;
    const int m0 = blockIdx.y * 128, n0 = blockIdx.x * NT;
    const int NP = TileCfg<NT>::NP;
    const int BUF = TileCfg<NT>::BUF;
    const int TB = TileCfg<NT>::TB;

    float acc[2][2*TileCfg<NT>::NP][4];
    #pragma unroll
    for (int i = 0; i < 2; i++)
        #pragma unroll
        for (int j = 0; j < 2*NP; j++)
            #pragma unroll
            for (int e = 0; e < 4; e++) acc[i][j][e] = 0.f;

    load_tiles<NT>(Ah, Al, Bh, Bl, M, N, m0, n0, 0, sb, tid);
    CP_COMMIT();
    load_tiles<NT>(Ah, Al, Bh, Bl, M, N, m0, n0, 1, sb + BUF, tid);
    CP_COMMIT();

    int cur = 0;
    const int aRow = (lane & 15);
    const int aCol = (lane >> 4) << 3;
    const int bRow = (lane & 7) + (((lane >> 4) & 1) << 3);
    const int bCol = ((lane >> 3) & 1) << 3;

    #pragma unroll 1
    for (int ch = 0; ch < 16; ch++) {
        if (ch == 15) { CP_WAIT0(); } else { CP_WAIT1(); }
        __syncthreads();
        if (ch + 2 < 16) {
            int nb = cur + 2; if (nb >= 3) nb -= 3;
            load_tiles<NT>(Ah, Al, Bh, Bl, M, N, m0, n0, ch + 2, sb + nb*BUF, tid);
            CP_COMMIT();
        }
        const uint32_t sAh = sb + cur*BUF;
        const uint32_t sAl = sAh + TILE_A;
        const uint32_t sBh = sAh + 2*TILE_A;
        const uint32_t sBl = sBh + TB;

        #pragma unroll
        for (int k16 = 0; k16 < 32; k16 += 16) {
            uint32_t ah[8], al[8];
            {
                uint32_t a0 = (uint32_t)((wm*32 + aRow)*STRIDE + k16 + aCol) * 2;
                uint32_t a1 = (uint32_t)((wm*32 + 16 + aRow)*STRIDE + k16 + aCol) * 2;
                ldm4(sAh + a0, ah);  ldm4(sAh + a1, ah + 4);
                ldm4(sAl + a0, al);  ldm4(sAl + a1, al + 4);
            }
            #pragma unroll
            for (int np = 0; np < NP; np++) {
                const int nb2 = wn*(NT/2) + np*16;
                const uint32_t boff = (uint32_t)((nb2 + bRow)*STRIDE + k16 + bCol) * 2;
                uint32_t bh[4], bl[4];
                ldm4(sBh + boff, bh);
                ldm4(sBl + boff, bl);
                const int na = np*2;
                #pragma unroll
                for (int mi = 0; mi < 2; mi++) {
                    mma16816(acc[mi][na],     ah + 4*mi, bh[0], bh[1]);
                    mma16816(acc[mi][na + 1], ah + 4*mi, bh[2], bh[3]);
                    mma16816(acc[mi][na],     ah + 4*mi, bl[0], bl[1]);
                    mma16816(acc[mi][na + 1], ah + 4*mi, bl[2], bl[3]);
                    mma16816(acc[mi][na],     al + 4*mi, bh[0], bh[1]);
                    mma16816(acc[mi][na + 1], al + 4*mi, bh[2], bh[3]);
                }
            }
        }
        cur++; if (cur == 3) cur = 0;
    }

    // epilogue
    const int r0 = m0 + wm*32 + (lane >> 2);
    const int c0 = n0 + wn*(NT/2) + (lane & 3) * 2;
    #pragma unroll
    for (int mi = 0; mi < 2; mi++) {
        #pragma unroll
        for (int na = 0; na < 2*NP; na++) {
            const int col = c0 + na*8;
            #pragma unroll
            for (int e = 0; e < 4; e++) {
                const int r = r0 + mi*16 + ((e >> 1) << 3);
                const int c = col + (e & 1);
                if (r >= M || c >= N) continue;
                float v = acc[mi][na][e];
                if (rowBias) v += rowBias[(size_t)(r >> 6) * N + c];
                if (colBias) v += colBias[c];
                if (C) C[(size_t)r * N + c] = v;
                if (Ch) {
                    bf16 hh, ll; split2(v, hh, ll);
                    Ch[(size_t)r * N + c] = hh;
                    Cl[(size_t)r * N + c] = ll;
                }
            }
        }
    }
}

__global__ void __launch_bounds__(256) gemm_plain64(
    const bf16* Ah, const bf16* Al, const bf16* Bh, const bf16* Bl,
    float* C, bf16* Ch, bf16* Cl, int M, int N,
    const float* rowBias, const float* colBias) {
    gemm_core<64>(Ah, Al, Bh, Bl, C, Ch, Cl, M, N, rowBias, colBias);
}

__global__ void __launch_bounds__(256) gemm_final128(
    const bf16* Ah, const bf16* Al, const bf16* Bh, const bf16* Bl,
    float* C, int M, int N, const float* colBias) {
    gemm_core<128>(Ah, Al, Bh, Bl, C, nullptr, nullptr, M, N, nullptr, colBias);
}

__global__ void __launch_bounds__(256) gemm_qkv3(
    const bf16* Ah, const bf16* Al, const bf16* wTH, const bf16* wTL, int l,
    float* q, float* k, float* v) {
    const int z = blockIdx.z;
    const size_t off = ((size_t)z*LLAYERS + l) * WSZ;
    float* C = (z == 0) ? q : (z == 1) ? k : v;
    gemm_core<64>(Ah, Al, wTH + off, wTL + off, C, nullptr, nullptr, NTOK, DMODEL, nullptr, nullptr);
}

__global__ void __launch_bounds__(256) gemm_cross12(
    const bf16* KinH, const bf16* KinL, const bf16* VinH, const bf16* VinL,
    const bf16* wTH, const bf16* wTL, float* kc, float* vc) {
    const int z = blockIdx.z, l = z >> 1, kv = z & 1;
    const size_t woff = ((size_t)(6 + kv)*LLAYERS + l) * WSZ;
    gemm_core<128>(kv ? VinH : KinH, kv ? VinL : KinL, wTH + woff, wTL + woff,
                   (kv ? vc : kc) + (size_t)l*CSZ, nullptr, nullptr, NCTOK, DMODEL, nullptr, nullptr);
}

__global__ void __launch_bounds__(256) gemm_gq6(
    const bf16* gH, const bf16* gL, const bf16* wTH, const bf16* wTL, float* gq) {
    const int l = blockIdx.z;
    const size_t woff = ((size_t)5*LLAYERS + l) * WSZ;
    gemm_core<64>(gH, gL, wTH + woff, wTL + woff,
                  gq + (size_t)l*NB*DMODEL, nullptr, nullptr, NB, DMODEL, nullptr, nullptr);
}

// ================= fused attention (fp32, register-blocked), writes hi/lo ======
#define ATTN_SMEM_FLOATS (3*64*65 + 8*512)
template<bool CAUSAL>
__global__ void attn_kernel(const float* __restrict__ Q, const float* __restrict__ Kb,
                            const float* __restrict__ Vb,
                            bf16* __restrict__ Oh, bf16* __restrict__ Ol,
                            int skeys, int kvTokens) {
    extern __shared__ float sm[];
    float* Qs = sm;
    float* Ks = sm + 64*65;
    float* Vs = sm + 2*64*65;
    float* Ps = sm + 3*64*65;     // [8 warps][8 rows][64 keys]

    const int b = blockIdx.x / NH, h = blockIdx.x % NH;
    const int tid = threadIdx.x, w = tid >> 5, lane = tid & 31;

    for (int i = tid; i < 64*64; i += 256) {
        int r = i >> 6, c = i & 63;
        Qs[r*65 + c] = Q[(size_t)(b*NS + r)*DMODEL + h*HD + c];
    }
    float mrow[8], lrow[8], a0[8], a1[8];
    #pragma unroll
    for (int i = 0; i < 8; i++) { mrow[i] = -1e30f; lrow[i] = 0.f; a0[i] = 0.f; a1[i] = 0.f; }
    __syncthreads();

    const int nch = (skeys + 63) >> 6;
    for (int ch = 0; ch < nch; ch++) {
        const int kb = ch * 64;
        const int cnt = min(64, skeys - kb);
        for (int i = tid; i < 64*64; i += 256) {
            int r = i >> 6, c = i & 63;
            float kv = 0.f, vv = 0.f;
            if (r < cnt) {
                size_t off = (size_t)(b*kvTokens + kb + r)*DMODEL + h*HD + c;
                kv = Kb[off]; vv = Vb[off];
            }
            Ks[r*65 + c] = kv; Vs[r*65 + c] = vv;
        }
        __syncthreads();

        // ---- phase 1: scores for all 8 rows at once ----
        float d0[8], d1[8];
        #pragma unroll
        for (int i = 0; i < 8; i++) { d0[i] = 0.f; d1[i] = 0.f; }
        #pragma unroll 4
        for (int d = 0; d < 64; d++) {
            float k0 = Ks[lane*65 + d];
            float k1 = Ks[(lane+32)*65 + d];
            #pragma unroll
            for (int rr = 0; rr < 8; rr++) {
                float qv = Qs[(w*8 + rr)*65 + d];
                d0[rr] += qv * k0;
                d1[rr] += qv * k1;
            }
        }

        // ---- per-row online softmax, probs to smem ----
        #pragma unroll
        for (int rr = 0; rr < 8; rr++) {
            const int r = w*8 + rr;
            float s0 = d0[rr] * 0.125f, s1 = d1[rr] * 0.125f;
            bool v0 = (lane      < cnt) && (!CAUSAL || (kb + lane)      <= r);
            bool v1 = (lane + 32 < cnt) && (!CAUSAL || (kb + lane + 32) <= r);
            if (!v0) s0 = -1e30f;
            if (!v1) s1 = -1e30f;
            float cm = fmaxf(s0, s1);
            #pragma unroll
            for (int o = 16; o > 0; o >>= 1) cm = fmaxf(cm, __shfl_xor_sync(0xffffffffu, cm, o));
            float nm = fmaxf(mrow[rr], cm);
            float corr = __expf(mrow[rr] - nm);
            float p0 = v0 ? __expf(s0 - nm) : 0.f;
            float p1 = v1 ? __expf(s1 - nm) : 0.f;
            float ps = p0 + p1;
            #pragma unroll
            for (int o = 16; o > 0; o >>= 1) ps += __shfl_xor_sync(0xffffffffu, ps, o);
            lrow[rr] = lrow[rr]*corr + ps;
            mrow[rr] = nm;
            a0[rr] *= corr; a1[rr] *= corr;
            Ps[w*512 + rr*64 + lane]      = p0;
            Ps[w*512 + rr*64 + lane + 32] = p1;
        }
        __syncwarp();

        // ---- phase 2: P @ V for all 8 rows at once ----
        #pragma unroll 4
        for (int kk = 0; kk < 64; kk++) {
            float v0 = Vs[kk*65 + lane];
            float v1 = Vs[kk*65 + lane + 32];
            #pragma unroll
            for (int rr = 0; rr < 8; rr++) {
                float p = Ps[w*512 + rr*64 + kk];
                a0[rr] += p * v0;
                a1[rr] += p * v1;
            }
        }
        __syncwarp();
        __syncthreads();
    }
    #pragma unroll
    for (int rr = 0; rr < 8; rr++) {
        int r = w*8 + rr;
        float inv = 1.0f / lrow[rr];
        size_t o = (size_t)(b*NS + r)*DMODEL + h*HD;
        float v0 = a0[rr] * inv, v1 = a1[rr] * inv;
        bf16 hh, ll;
        split2(v0, hh, ll); Oh[o + lane]      = hh; Ol[o + lane]      = ll;
        split2(v1, hh, ll); Oh[o + lane + 32] = hh; Ol[o + lane + 32] = ll;
    }
}

// ================= final row softmax over VOCAB (in-place) =================
__global__ void softmax_kernel(float* __restrict__ out) {
    __shared__ float buf[NVOCAB];
    __shared__ float red[8];
    const int tid = threadIdx.x, w = tid >> 5, lane = tid & 31;
    float* p = out + (size_t)blockIdx.x * NVOCAB;

    float mx = -1e30f;
    for (int i = tid; i < NVOCAB; i += 256) { float v = p[i]; buf[i] = v; mx = fmaxf(mx, v); }
    #pragma unroll
    for (int o = 16; o > 0; o >>= 1) mx = fmaxf(mx, __shfl_xor_sync(0xffffffffu, mx, o));
    if (lane == 0) red[w] = mx;
    __syncthreads();
    mx = red[0];
    #pragma unroll
    for (int i = 1; i < 8; i++) mx = fmaxf(mx, red[i]);
    __syncthreads();

    float sum = 0.f;
    for (int i = tid; i < NVOCAB; i += 256) { float e = __expf(buf[i] - mx); buf[i] = e; sum += e; }
    #pragma unroll
    for (int o = 16; o > 0; o >>= 1) sum += __shfl_xor_sync(0xffffffffu, sum, o);
    if (lane == 0) red[w] = sum;
    __syncthreads();
    sum = 0.f;
    #pragma unroll
    for (int i = 0; i < 8; i++) sum += red[i];
    float inv = 1.0f / sum;
    for (int i = tid; i < NVOCAB; i += 256) p[i] = buf[i] * inv;
}

// ================= host launcher =================
extern "C" void kernel_launch(void* const* d_in, const int* in_sizes, int n_in,
                              void* d_out, int out_size) {
    const int*   x   = (const int*)  d_in[0];
    const float* Kin = (const float*)d_in[1];
    const float* Vin = (const float*)d_in[2];
    const float* g   = (const float*)d_in[3];
    int i = 4;
    if (i < n_in && in_sizes[i] == 1) i++;
    const float* emb  = (const float*)d_in[i++];
    const float* Wq_s = (const float*)d_in[i++];
    const float* Wk_s = (const float*)d_in[i++];
    const float* Wv_s = (const float*)d_in[i++];
    const float* Wo_s = (const float*)d_in[i++];
    const float* Wq_c = (const float*)d_in[i++];
    const float* Wg_c = (const float*)d_in[i++];
    const float* Wk_c = (const float*)d_in[i++];
    const float* Wv_c = (const float*)d_in[i++];
    const float* Wo_c = (const float*)d_in[i++];
    const float* Wf   = (const float*)d_in[i++];
    const float* bf   = (const float*)d_in[i++];

    bf16 *actH, *actL, *aoH, *aoL, *KinH, *KinL, *VinH, *VinL, *gH, *gL, *wTH, *wTL, *wfTH, *wfTL;
    float *q, *k, *v, *kc, *vc, *gq;
    cudaGetSymbolAddress((void**)&actH, g_actH);  cudaGetSymbolAddress((void**)&actL, g_actL);
    cudaGetSymbolAddress((void**)&aoH,  g_aoH);   cudaGetSymbolAddress((void**)&aoL,  g_aoL);
    cudaGetSymbolAddress((void**)&KinH, g_KinH);  cudaGetSymbolAddress((void**)&KinL, g_KinL);
    cudaGetSymbolAddress((void**)&VinH, g_VinH);  cudaGetSymbolAddress((void**)&VinL, g_VinL);
    cudaGetSymbolAddress((void**)&gH,   g_gH);    cudaGetSymbolAddress((void**)&gL,   g_gL);
    cudaGetSymbolAddress((void**)&wTH,  g_wTH);   cudaGetSymbolAddress((void**)&wTL,  g_wTL);
    cudaGetSymbolAddress((void**)&wfTH, g_wfTH);  cudaGetSymbolAddress((void**)&wfTL, g_wfTL);
    cudaGetSymbolAddress((void**)&q,  g_q);  cudaGetSymbolAddress((void**)&k, g_k);
    cudaGetSymbolAddress((void**)&v,  g_v);
    cudaGetSymbolAddress((void**)&kc, g_kc); cudaGetSymbolAddress((void**)&vc, g_vc);
    cudaGetSymbolAddress((void**)&gq, g_gq);

    const int ATTN_SMEM = ATTN_SMEM_FLOATS * (int)sizeof(float);
    cudaFuncSetAttribute(attn_kernel<true>,  cudaFuncAttributeMaxDynamicSharedMemorySize, ATTN_SMEM);
    cudaFuncSetAttribute(attn_kernel<false>, cudaFuncAttributeMaxDynamicSharedMemorySize, ATTN_SMEM);
    cudaFuncSetAttribute(gemm_plain64,  cudaFuncAttributeMaxDynamicSharedMemorySize, TileCfg<64>::SMEM);
    cudaFuncSetAttribute(gemm_qkv3,     cudaFuncAttributeMaxDynamicSharedMemorySize, TileCfg<64>::SMEM);
    cudaFuncSetAttribute(gemm_gq6,      cudaFuncAttributeMaxDynamicSharedMemorySize, TileCfg<64>::SMEM);
    cudaFuncSetAttribute(gemm_cross12,  cudaFuncAttributeMaxDynamicSharedMemorySize, TileCfg<128>::SMEM);
    cudaFuncSetAttribute(gemm_final128, cudaFuncAttributeMaxDynamicSharedMemorySize, TileCfg<128>::SMEM);

    // weight transpose + split
    WPtrs wp;
    wp.p[0]=Wq_s; wp.p[1]=Wk_s; wp.p[2]=Wv_s; wp.p[3]=Wo_s; wp.p[4]=Wq_c;
    wp.p[5]=Wg_c; wp.p[6]=Wk_c; wp.p[7]=Wv_c; wp.p[8]=Wo_c;
    wconv_all_kernel<<<dim3(16, 16, 9*LLAYERS), dim3(32, 8)>>>(wp, wTH, wTL);
    wconv_kernel<<<dim3((NVOCAB + 31)/32, 16, 1), dim3(32, 8)>>>(Wf, wfTH, wfTL, DMODEL, NVOCAB);

    // input splits (element counts divisible by 4)
    split_kernel<<<((int)CSZ/4 + 255)/256, 256>>>(Kin, KinH, KinL, (int)CSZ);
    split_kernel<<<((int)CSZ/4 + 255)/256, 256>>>(Vin, VinH, VinL, (int)CSZ);
    split_kernel<<<(NB*DMODEL/4 + 255)/256, 256>>>(g, gH, gL, NB*DMODEL);

    embed_kernel<<<NTOK, 128>>>(x, emb, actH, actL);

    // layer-independent projections
    gemm_gq6    <<<dim3(8, 1, LLAYERS), 256, TileCfg<64>::SMEM>>>(gH, gL, wTH, wTL, gq);
    gemm_cross12<<<dim3(4, NCTOK/128, 2*LLAYERS), 256, TileCfg<128>::SMEM>>>(
        KinH, KinL, VinH, VinL, wTH, wTL, kc, vc);

    for (int l = 0; l < LLAYERS; l++) {
        gemm_qkv3<<<dim3(8, NTOK/128, 3), 256, TileCfg<64>::SMEM>>>(actH, actL, wTH, wTL, l, q, k, v);
        attn_kernel<true><<<NB*NH, 256, ATTN_SMEM>>>(q, k, v, aoH, aoL, NS, NS);
        gemm_plain64<<<dim3(8, NTOK/128), 256, TileCfg<64>::SMEM>>>(
            aoH, aoL, wTH + ((size_t)3*LLAYERS + l)*WSZ, wTL + ((size_t)3*LLAYERS + l)*WSZ,
            nullptr, actH, actL, NTOK, DMODEL, nullptr, nullptr);

        gemm_plain64<<<dim3(8, NTOK/128), 256, TileCfg<64>::SMEM>>>(
            actH, actL, wTH + ((size_t)4*LLAYERS + l)*WSZ, wTL + ((size_t)4*LLAYERS + l)*WSZ,
            q, nullptr, nullptr, NTOK, DMODEL, gq + (size_t)l*NB*DMODEL, nullptr);
        attn_kernel<false><<<NB*NH, 256, ATTN_SMEM>>>(
            q, kc + (size_t)l*CSZ, vc + (size_t)l*CSZ, aoH, aoL, NNR, NNR);
        gemm_plain64<<<dim3(8, NTOK/128), 256, TileCfg<64>::SMEM>>>(
            aoH, aoL, wTH + ((size_t)8*LLAYERS + l)*WSZ, wTL + ((size_t)8*LLAYERS + l)*WSZ,
            nullptr, actH, actL, NTOK, DMODEL, nullptr, nullptr);
    }

    gemm_final128<<<dim3((NVOCAB + 127)/128, NTOK/128), 256, TileCfg<128>::SMEM>>>(
        actH, actL, wfTH, wfTL, (float*)d_out, NTOK, NVOCAB, bf);
    softmax_kernel<<<NTOK, 256>>>((float*)d_out);
}